// round 9
// baseline (speedup 1.0000x reference)
#include <cuda_runtime.h>
#include <cuda_bf16.h>
#include <math.h>
#include <stdint.h>

#define N_GRID 4096
#define NH     2048
#define SPLITS 8
#define MAXB   1024

// ---------------- device scratch ----------------
__device__ __nv_bfloat16 g_CsF_hi[2 * 128 * NH];
__device__ __nv_bfloat16 g_CsF_lo[2 * 128 * NH];
__device__ __nv_bfloat16 g_CsT_hi[2 * NH * 128];
__device__ __nv_bfloat16 g_CsT_lo[2 * NH * 128];
__device__ float         g_part  [16 * MAXB * 128];
__device__ __nv_bfloat16 g_Ae_hi[MAXB * 128];
__device__ __nv_bfloat16 g_Ae_lo[MAXB * 128];
__device__ __nv_bfloat16 g_Ao_hi[MAXB * 128];
__device__ __nv_bfloat16 g_Ao_lo[MAXB * 128];

// ---------------- helpers ----------------
__device__ __forceinline__ uint32_t smem_u32(const void* p) {
    uint32_t a;
    asm("{ .reg .u64 t; cvta.to.shared.u64 t, %1; cvt.u32.u64 %0, t; }" : "=r"(a) : "l"(p));
    return a;
}
__device__ __forceinline__ uint32_t swz(uint32_t off) { return off ^ ((off >> 3) & 0x70); }

__device__ __forceinline__ void cp16(uint32_t dst, const void* src) {
    asm volatile("cp.async.cg.shared.global [%0], [%1], 16;" :: "r"(dst), "l"(src));
}
__device__ __forceinline__ void cp_commit() {
    asm volatile("cp.async.commit_group;" ::: "memory");
}
template <int N>
__device__ __forceinline__ void cp_wait() {
    asm volatile("cp.async.wait_group %0;" :: "n"(N) : "memory");
}

__device__ __forceinline__ void ldsm_x4(uint32_t& r0, uint32_t& r1, uint32_t& r2, uint32_t& r3,
                                        uint32_t addr) {
    asm volatile("ldmatrix.sync.aligned.m8n8.x4.shared.b16 {%0,%1,%2,%3}, [%4];"
                 : "=r"(r0), "=r"(r1), "=r"(r2), "=r"(r3) : "r"(addr));
}
__device__ __forceinline__ void ldsm_x2(uint32_t& r0, uint32_t& r1, uint32_t addr) {
    asm volatile("ldmatrix.sync.aligned.m8n8.x2.shared.b16 {%0,%1}, [%2];"
                 : "=r"(r0), "=r"(r1) : "r"(addr));
}
__device__ __forceinline__ void mma_bf16(float* c, uint32_t a0, uint32_t a1, uint32_t a2,
                                         uint32_t a3, uint32_t b0, uint32_t b1) {
    asm volatile("mma.sync.aligned.m16n8k16.row.col.f32.bf16.bf16.f32 "
                 "{%0,%1,%2,%3}, {%4,%5,%6,%7}, {%8,%9}, {%0,%1,%2,%3};"
                 : "+f"(c[0]), "+f"(c[1]), "+f"(c[2]), "+f"(c[3])
                 : "r"(a0), "r"(a1), "r"(a2), "r"(a3), "r"(b0), "r"(b1));
}

__device__ __forceinline__ void split2(float v, __nv_bfloat16& h, __nv_bfloat16& l) {
    h = __float2bfloat16(v);
    l = __float2bfloat16(v - __bfloat162float(h));
}

// ---------------------------------------------------------------------------
__device__ __forceinline__ float cos_acc(float x) {
    const float INV_PIO2 = 0.6366197723675814f;
    float qf = rintf(x * INV_PIO2);
    int   iq = (int)qf;
    const float HI = 1.57079637050628662109375f;
    const float MD = -4.3711388286737929e-08f;
    const float LO = -1.7151245100059657e-15f;
    float r = fmaf(-qf, HI, x);
    r = fmaf(-qf, MD, r);
    r = fmaf(-qf, LO, r);
    float r2 = r * r;
    float pc = fmaf(r2,  2.4390448796e-05f, -1.3886763775e-03f);
    pc = fmaf(r2, pc,  4.1666623323e-02f);
    pc = fmaf(r2, pc, -4.9999999725e-01f);
    pc = fmaf(r2, pc,  1.0f);
    float ps = fmaf(r2,  2.7183114939e-06f, -1.9839334836e-04f);
    ps = fmaf(r2, ps,  8.3333293859e-03f);
    ps = fmaf(r2, ps, -1.6666666642e-01f);
    ps = r * fmaf(r2, ps, 1.0f);
    int n = iq & 3;
    float v = (n & 1) ? ps : pc;
    if (n == 1 || n == 2) v = -v;
    return v;
}

__device__ __forceinline__ float cs_val(int n, int k) {
    const float PI_F = 3.1415927410125732421875f;
    float t1 = PI_F * (float)(2 * n + 1);
    float theta = (t1 * (float)k) * (1.0f / 8192.0f);
    const float SCALE = 0.02209708691f;
    return SCALE * cos_acc(theta);
}

// ---------------------------------------------------------------------------
// prep: Cs tables only (rho fold is fused into gemm1 now)
// ---------------------------------------------------------------------------
__global__ void prep_kernel() {
    int bx = blockIdx.x;
    if (bx < 2048) {
        int t = bx * 256 + threadIdx.x;            // [g][kp][np]
        int g = t >> 18;
        int rem = t & 0x3FFFF;
        int kp = rem >> 11, np = rem & (NH - 1);
        int k = g ? (2 * kp + 1) : (2 * kp + 2);
        float v = cs_val(np, k);
        __nv_bfloat16 h, l;
        split2(v, h, l);
        g_CsF_hi[t] = h; g_CsF_lo[t] = l;
    } else {
        int t = (bx - 2048) * 256 + threadIdx.x;   // [g][np][kp]
        int g = t >> 18;
        int rem = t & 0x3FFFF;
        int np = rem >> 7, kp = rem & 127;
        int k = g ? (2 * kp + 1) : (2 * kp + 2);
        float v = cs_val(np, k);
        __nv_bfloat16 h, l;
        split2(v, h, l);
        g_CsT_hi[t] = h; g_CsT_lo[t] = l;
    }
}

// ---------------------------------------------------------------------------
__device__ __forceinline__ void tile_async(uint32_t dst, const __nv_bfloat16* src,
                                           int stride, int tid) {          // 128x64
    const int row = tid >> 2;
    const int c0 = tid & 3;
    const char* s = (const char*)(src + (size_t)row * stride);
#pragma unroll
    for (int i = 0; i < 2; i++) {
        int ch = c0 + i * 4;
        cp16(dst + swz((uint32_t)row * 128 + ch * 16), s + ch * 16);
    }
}

// one 64-wide K step; warp tile 32x32 (mi=2, nj=4); term-outer ordering
template <int ALO, int BLO>
__device__ __forceinline__ void compute_step(uint32_t aB, uint32_t bB, int wm, int wn,
                                             int lane, float acc[2][4][4]) {
    const uint32_t aRow = (uint32_t)(wm * 32 + (lane & 15)) * 128 + ((lane >> 4) << 4);
    const uint32_t bRow = (uint32_t)(wn * 32 + (lane & 7)) * 128 + (((lane >> 3) & 1) << 4);
#pragma unroll
    for (int k16 = 0; k16 < 4; k16++) {
        const uint32_t kb = k16 * 32;
        uint32_t aH[2][4], aL[2][4];
#pragma unroll
        for (int mi = 0; mi < 2; mi++) {
            uint32_t off = swz(aRow + mi * 16 * 128 + kb);
            ldsm_x4(aH[mi][0], aH[mi][1], aH[mi][2], aH[mi][3], aB + off);
            ldsm_x4(aL[mi][0], aL[mi][1], aL[mi][2], aL[mi][3], aB + ALO + off);
        }
        uint32_t bH[4][2], bL[4][2];
#pragma unroll
        for (int nj = 0; nj < 4; nj++) {
            uint32_t off = swz(bRow + nj * 8 * 128 + kb);
            ldsm_x2(bH[nj][0], bH[nj][1], bB + off);
            ldsm_x2(bL[nj][0], bL[nj][1], bB + BLO + off);
        }
#pragma unroll
        for (int mi = 0; mi < 2; mi++)
#pragma unroll
            for (int nj = 0; nj < 4; nj++)
                mma_bf16(acc[mi][nj], aH[mi][0], aH[mi][1], aH[mi][2], aH[mi][3], bH[nj][0], bH[nj][1]);
#pragma unroll
        for (int mi = 0; mi < 2; mi++)
#pragma unroll
            for (int nj = 0; nj < 4; nj++)
                mma_bf16(acc[mi][nj], aH[mi][0], aH[mi][1], aH[mi][2], aH[mi][3], bL[nj][0], bL[nj][1]);
#pragma unroll
        for (int mi = 0; mi < 2; mi++)
#pragma unroll
            for (int nj = 0; nj < 4; nj++)
                mma_bf16(acc[mi][nj], aL[mi][0], aL[mi][1], aL[mi][2], aL[mi][3], bH[nj][0], bH[nj][1]);
    }
}

// ---------------------------------------------------------------------------
// GEMM1 v2 (fold fused): grid (8, 2, SPLITS), block 512.
// A: LDG rho fp32 fwd+bwd -> fold -> split -> STS, 2-slot ring (64KB).
// B: CsF via cp.async, 3-slot ring (96KB). smem 160KB.
// ---------------------------------------------------------------------------
#define G1_B_BASE 65536
#define SMEM1_BYTES (65536 + 3 * 32768)

__global__ __launch_bounds__(512) void gemm1_hmma(const float* __restrict__ rho, int Brows) {
    extern __shared__ char sm[];
    const uint32_t sb = smem_u32(sm);
    const int tid = threadIdx.x, wid = tid >> 5, lane = tid & 31;
    const int wm = wid & 3, wn = wid >> 2;
    const int mt = blockIdx.x, grp = blockIdx.y, sp = blockIdx.z;
    const int k0 = sp * (NH / SPLITS);              // 256-chunk
    const int NS = 4;

    float acc[2][4][4];
#pragma unroll
    for (int a = 0; a < 2; a++)
#pragma unroll
        for (int b = 0; b < 4; b++)
#pragma unroll
            for (int c = 0; c < 4; c++) acc[a][b][c] = 0.0f;

    const __nv_bfloat16* bHsrc = g_CsF_hi + (size_t)grp * 128 * NH + k0;
    const __nv_bfloat16* bLsrc = g_CsF_lo + (size_t)grp * 128 * NH + k0;

    // A LDG lanes: thread -> row (tid>>2), 16 cols at (tid&3)*16
    const int arow = tid >> 2;
    const int ac0 = (tid & 3) * 16;
    const float* rbase = rho + (size_t)(mt * 128 + arow) * N_GRID;

    float4 fv[4], bv[4];
#define LDGA(s)                                                         \
    do {                                                                \
        int kg_ = k0 + (s) * 64 + ac0;                                  \
        _Pragma("unroll")                                               \
        for (int i = 0; i < 4; i++) {                                   \
            fv[i] = *(const float4*)(rbase + kg_ + 4 * i);              \
            bv[i] = *(const float4*)(rbase + 4092 - (kg_ + 4 * i));     \
        }                                                               \
    } while (0)

#define G1BFILL(slot, ko)                                               \
    do {                                                                \
        uint32_t st_ = sb + G1_B_BASE + (slot) * 32768;                 \
        tile_async(st_,         bHsrc + (ko), NH, tid);                 \
        tile_async(st_ + 16384, bLsrc + (ko), NH, tid);                 \
        cp_commit();                                                    \
    } while (0)

    LDGA(0);
    G1BFILL(0, 0);
    G1BFILL(1, 64);

    for (int s = 0; s < NS; s++) {
        // convert + STS A(s) into slot s%2
        {
            uint32_t abase = sb + (s & 1) * 32768;
#pragma unroll
            for (int i = 0; i < 4; i++) {
                float u0, u1, u2, u3;
                if (grp) {
                    u0 = fv[i].x - bv[i].w; u1 = fv[i].y - bv[i].z;
                    u2 = fv[i].z - bv[i].y; u3 = fv[i].w - bv[i].x;
                } else {
                    u0 = fv[i].x + bv[i].w; u1 = fv[i].y + bv[i].z;
                    u2 = fv[i].z + bv[i].y; u3 = fv[i].w + bv[i].x;
                }
                __nv_bfloat16 h[4], l[4];
                split2(u0, h[0], l[0]); split2(u1, h[1], l[1]);
                split2(u2, h[2], l[2]); split2(u3, h[3], l[3]);
                uint32_t off = swz((uint32_t)arow * 128 + (ac0 + 4 * i) * 2);
                *(uint2*)(sm + (s & 1) * 32768 + off)         = *(uint2*)h;
                *(uint2*)(sm + (s & 1) * 32768 + 16384 + off) = *(uint2*)l;
                (void)abase;
            }
        }
        if (s + 1 < NS) LDGA(s + 1);
        if (s + 2 < NS) G1BFILL((s + 2) % 3, (s + 2) * 64);
        if (s + 2 < NS) cp_wait<2>(); else if (s + 1 < NS) cp_wait<1>(); else cp_wait<0>();
        __syncthreads();
        compute_step<16384, 16384>(sb + (s & 1) * 32768,
                                   sb + G1_B_BASE + (s % 3) * 32768, wm, wn, lane, acc);
        __syncthreads();
    }

    const int g = lane >> 2, tig = lane & 3;
    const int mbase = mt * 128 + wm * 32;
    const int nbase = wn * 32;
#pragma unroll
    for (int mi = 0; mi < 2; mi++)
#pragma unroll
        for (int nj = 0; nj < 4; nj++) {
            int row = mbase + mi * 16 + g;
            int col = nbase + nj * 8 + tig * 2;
            float* p0 = g_part + ((size_t)(grp * SPLITS + sp) * Brows + row) * 128 + col;
            *(float2*)p0             = make_float2(acc[mi][nj][0], acc[mi][nj][1]);
            *(float2*)(p0 + 8 * 128) = make_float2(acc[mi][nj][2], acc[mi][nj][3]);
        }
}

__global__ void reduce_lam_kernel(const float* __restrict__ ms, int Brows) {
    int g = blockIdx.y;
    int idx = blockIdx.x * blockDim.x + threadIdx.x;
    int kp = idx & 127;
    float sum = 0.0f;
#pragma unroll
    for (int s = 0; s < SPLITS; s++)
        sum += g_part[(size_t)(g * SPLITS + s) * Brows * 128 + idx];
    float v = ms[g ? (2 * kp) : (2 * kp + 1)] * sum;
    __nv_bfloat16 h, l;
    split2(v, h, l);
    if (g) { g_Ao_hi[idx] = h; g_Ao_lo[idx] = l; }
    else   { g_Ae_hi[idx] = h; g_Ae_lo[idx] = l; }
}

// ---------------------------------------------------------------------------
// GEMM2 v4: grid (8, 16), block 512. B resident (128KB), A streamed per kc
// (64KB single buffer). Warps 4x4, tile 32x32 dual-e/o; register epilogue.
// smem layout: A slot: eo*32768 + op*16384 (64KB at 0)
//              B: 65536 + eo*65536 + op*32768 + kc*16384 (128KB)
// ---------------------------------------------------------------------------
#define G2_B_BASE 65536
#define SMEM2_BYTES 196608

__global__ __launch_bounds__(512) void gemm2_hmma(float* __restrict__ phi) {
    extern __shared__ char sm[];
    const uint32_t sb = smem_u32(sm);
    const int tid = threadIdx.x, wid = tid >> 5, lane = tid & 31;
    const int wm = wid & 3, wn = wid >> 2;
    const int mt = blockIdx.x, nt = blockIdx.y;
    const size_t aoff = (size_t)(mt * 128) * 128;

#define G2AFILL(kc)                                                          \
    do {                                                                     \
        tile_async(sb,         g_Ae_hi + aoff + (kc) * 64, 128, tid);        \
        tile_async(sb + 16384, g_Ae_lo + aoff + (kc) * 64, 128, tid);        \
        tile_async(sb + 32768, g_Ao_hi + aoff + (kc) * 64, 128, tid);        \
        tile_async(sb + 49152, g_Ao_lo + aoff + (kc) * 64, 128, tid);        \
        cp_commit();                                                         \
    } while (0)

    // resident B fill: 8 tiles
    {
        const size_t be = (size_t)(nt * 128) * 128;
        const size_t bo = (size_t)NH * 128 + be;
#pragma unroll
        for (int kc = 0; kc < 2; kc++) {
            tile_async(sb + G2_B_BASE +          kc * 16384, g_CsT_hi + be + kc * 64, 128, tid);
            tile_async(sb + G2_B_BASE + 32768 +  kc * 16384, g_CsT_lo + be + kc * 64, 128, tid);
            tile_async(sb + G2_B_BASE + 65536 +  kc * 16384, g_CsT_hi + bo + kc * 64, 128, tid);
            tile_async(sb + G2_B_BASE + 98304 +  kc * 16384, g_CsT_lo + bo + kc * 64, 128, tid);
        }
        cp_commit();
    }
    G2AFILL(0);

    const uint32_t aRow = (uint32_t)(wm * 32 + (lane & 15)) * 128 + ((lane >> 4) << 4);
    const uint32_t bRow = (uint32_t)(wn * 32 + (lane & 7)) * 128 + (((lane >> 3) & 1) << 4);
    const int g = lane >> 2, tig = lane & 3;

    float acc[2][2][4][4];                  // [eo][mi][nj][4]
#pragma unroll
    for (int e = 0; e < 2; e++)
#pragma unroll
        for (int a = 0; a < 2; a++)
#pragma unroll
            for (int b = 0; b < 4; b++)
#pragma unroll
                for (int c = 0; c < 4; c++) acc[e][a][b][c] = 0.0f;

    for (int kc = 0; kc < 2; kc++) {
        cp_wait<0>();
        __syncthreads();
#pragma unroll
        for (int k16 = 0; k16 < 4; k16++) {
            const uint32_t kb = k16 * 32;
#pragma unroll
            for (int eo = 0; eo < 2; eo++) {
                uint32_t aBase = sb + eo * 32768u;
                uint32_t bBase = sb + G2_B_BASE + eo * 65536u + kc * 16384u;
                uint32_t aH[2][4], aL[2][4];
#pragma unroll
                for (int mi = 0; mi < 2; mi++) {
                    uint32_t off = swz(aRow + mi * 16 * 128 + kb);
                    ldsm_x4(aH[mi][0], aH[mi][1], aH[mi][2], aH[mi][3], aBase + off);
                    ldsm_x4(aL[mi][0], aL[mi][1], aL[mi][2], aL[mi][3], aBase + 16384u + off);
                }
                uint32_t bH[4][2], bL[4][2];
#pragma unroll
                for (int nj = 0; nj < 4; nj++) {
                    uint32_t off = swz(bRow + nj * 8 * 128 + kb);
                    ldsm_x2(bH[nj][0], bH[nj][1], bBase + off);
                    ldsm_x2(bL[nj][0], bL[nj][1], bBase + 32768u + off);
                }
#pragma unroll
                for (int mi = 0; mi < 2; mi++)
#pragma unroll
                    for (int nj = 0; nj < 4; nj++)
                        mma_bf16(acc[eo][mi][nj], aH[mi][0], aH[mi][1], aH[mi][2], aH[mi][3],
                                 bH[nj][0], bH[nj][1]);
#pragma unroll
                for (int mi = 0; mi < 2; mi++)
#pragma unroll
                    for (int nj = 0; nj < 4; nj++)
                        mma_bf16(acc[eo][mi][nj], aH[mi][0], aH[mi][1], aH[mi][2], aH[mi][3],
                                 bL[nj][0], bL[nj][1]);
#pragma unroll
                for (int mi = 0; mi < 2; mi++)
#pragma unroll
                    for (int nj = 0; nj < 4; nj++)
                        mma_bf16(acc[eo][mi][nj], aL[mi][0], aL[mi][1], aL[mi][2], aL[mi][3],
                                 bH[nj][0], bH[nj][1]);
            }
        }
        __syncthreads();                    // all warps done with A(kc)
        if (kc == 0) G2AFILL(1);
    }

    // register epilogue: phi[n'] = e + o ; phi[4095-n'] = e - o
#pragma unroll
    for (int mi = 0; mi < 2; mi++)
#pragma unroll
        for (int nj = 0; nj < 4; nj++) {
#pragma unroll
            for (int half = 0; half < 2; half++) {
                int row = mt * 128 + wm * 32 + mi * 16 + half * 8 + g;
                int c = nt * 128 + wn * 32 + nj * 8 + tig * 2;
                float e0 = acc[0][mi][nj][half * 2];
                float e1 = acc[0][mi][nj][half * 2 + 1];
                float o0 = acc[1][mi][nj][half * 2];
                float o1 = acc[1][mi][nj][half * 2 + 1];
                float* rowp = phi + (size_t)row * N_GRID;
                *(float2*)(rowp + c) = make_float2(e0 + o0, e1 + o1);
                *(float2*)(rowp + (4094 - c)) = make_float2(e1 - o1, e0 - o0);
            }
        }
}

// ---------------------------------------------------------------------------
extern "C" void kernel_launch(void* const* d_in, const int* in_sizes, int n_in,
                              void* d_out, int out_size) {
    const float* rho = (const float*)d_in[0];
    const float* ms  = (const float*)d_in[1];
    float* phi = (float*)d_out;
    const int Brows = in_sizes[0] / N_GRID;

    cudaFuncSetAttribute(gemm1_hmma, cudaFuncAttributeMaxDynamicSharedMemorySize, SMEM1_BYTES);
    cudaFuncSetAttribute(gemm2_hmma, cudaFuncAttributeMaxDynamicSharedMemorySize, SMEM2_BYTES);

    prep_kernel<<<4096, 256>>>();

    dim3 g1(Brows / 128, 2, SPLITS);
    gemm1_hmma<<<g1, 512, SMEM1_BYTES>>>(rho, Brows);

    dim3 gr((Brows * 128) / 256, 2);
    reduce_lam_kernel<<<gr, 256>>>(ms, Brows);

    dim3 g2(Brows / 128, NH / 128);
    gemm2_hmma<<<g2, 512, SMEM2_BYTES>>>(phi);
}

// round 10
// speedup vs baseline: 1.1188x; 1.1188x over previous
#include <cuda_runtime.h>
#include <cuda_bf16.h>
#include <math.h>
#include <stdint.h>

#define N_GRID 4096
#define NH     2048
#define SPLITS 8
#define MAXB   1024

// ---------------- device scratch ----------------
__device__ __nv_bfloat16 g_uP_hi[MAXB * NH];
__device__ __nv_bfloat16 g_uP_lo[MAXB * NH];
__device__ __nv_bfloat16 g_uM_hi[MAXB * NH];
__device__ __nv_bfloat16 g_uM_lo[MAXB * NH];
__device__ __nv_bfloat16 g_CsF_hi[2 * 128 * NH];
__device__ __nv_bfloat16 g_CsF_lo[2 * 128 * NH];
__device__ __nv_bfloat16 g_CsT_hi[2 * NH * 128];
__device__ __nv_bfloat16 g_CsT_lo[2 * NH * 128];
__device__ float         g_part  [16 * MAXB * 128];
__device__ __nv_bfloat16 g_Ae_hi[MAXB * 128];
__device__ __nv_bfloat16 g_Ae_lo[MAXB * 128];
__device__ __nv_bfloat16 g_Ao_hi[MAXB * 128];
__device__ __nv_bfloat16 g_Ao_lo[MAXB * 128];

// ---------------- helpers ----------------
__device__ __forceinline__ uint32_t smem_u32(const void* p) {
    uint32_t a;
    asm("{ .reg .u64 t; cvta.to.shared.u64 t, %1; cvt.u32.u64 %0, t; }" : "=r"(a) : "l"(p));
    return a;
}
__device__ __forceinline__ uint32_t swz(uint32_t off) { return off ^ ((off >> 3) & 0x70); }

__device__ __forceinline__ void cp16(uint32_t dst, const void* src) {
    asm volatile("cp.async.cg.shared.global [%0], [%1], 16;" :: "r"(dst), "l"(src));
}
__device__ __forceinline__ void cp_commit() {
    asm volatile("cp.async.commit_group;" ::: "memory");
}
template <int N>
__device__ __forceinline__ void cp_wait() {
    asm volatile("cp.async.wait_group %0;" :: "n"(N) : "memory");
}

__device__ __forceinline__ void ldsm_x4(uint32_t& r0, uint32_t& r1, uint32_t& r2, uint32_t& r3,
                                        uint32_t addr) {
    asm volatile("ldmatrix.sync.aligned.m8n8.x4.shared.b16 {%0,%1,%2,%3}, [%4];"
                 : "=r"(r0), "=r"(r1), "=r"(r2), "=r"(r3) : "r"(addr));
}
__device__ __forceinline__ void mma_bf16(float* c, uint32_t a0, uint32_t a1, uint32_t a2,
                                         uint32_t a3, uint32_t b0, uint32_t b1) {
    asm volatile("mma.sync.aligned.m16n8k16.row.col.f32.bf16.bf16.f32 "
                 "{%0,%1,%2,%3}, {%4,%5,%6,%7}, {%8,%9}, {%0,%1,%2,%3};"
                 : "+f"(c[0]), "+f"(c[1]), "+f"(c[2]), "+f"(c[3])
                 : "r"(a0), "r"(a1), "r"(a2), "r"(a3), "r"(b0), "r"(b1));
}

__device__ __forceinline__ void split2(float v, __nv_bfloat16& h, __nv_bfloat16& l) {
    h = __float2bfloat16(v);
    l = __float2bfloat16(v - __bfloat162float(h));
}

// ---------------------------------------------------------------------------
__device__ __forceinline__ float cos_acc(float x) {
    const float INV_PIO2 = 0.6366197723675814f;
    float qf = rintf(x * INV_PIO2);
    int   iq = (int)qf;
    const float HI = 1.57079637050628662109375f;
    const float MD = -4.3711388286737929e-08f;
    const float LO = -1.7151245100059657e-15f;
    float r = fmaf(-qf, HI, x);
    r = fmaf(-qf, MD, r);
    r = fmaf(-qf, LO, r);
    float r2 = r * r;
    float pc = fmaf(r2,  2.4390448796e-05f, -1.3886763775e-03f);
    pc = fmaf(r2, pc,  4.1666623323e-02f);
    pc = fmaf(r2, pc, -4.9999999725e-01f);
    pc = fmaf(r2, pc,  1.0f);
    float ps = fmaf(r2,  2.7183114939e-06f, -1.9839334836e-04f);
    ps = fmaf(r2, ps,  8.3333293859e-03f);
    ps = fmaf(r2, ps, -1.6666666642e-01f);
    ps = r * fmaf(r2, ps, 1.0f);
    int n = iq & 3;
    float v = (n & 1) ? ps : pc;
    if (n == 1 || n == 2) v = -v;
    return v;
}

__device__ __forceinline__ float cs_val(int n, int k) {
    const float PI_F = 3.1415927410125732421875f;
    float t1 = PI_F * (float)(2 * n + 1);
    float theta = (t1 * (float)k) * (1.0f / 8192.0f);
    const float SCALE = 0.02209708691f;
    return SCALE * cos_acc(theta);
}

// ---------------------------------------------------------------------------
// prep: fold rho -> u hi/lo ; build folded Cs tables (identity-based)
// ---------------------------------------------------------------------------
__global__ void prep_kernel(const float* __restrict__ rho) {
    int bx = blockIdx.x;
    if (bx < 2048) {
        int t = bx * 256 + threadIdx.x;
        int b = t >> 9;
        int np = (t & 511) * 4;
        float4 f = *(const float4*)(rho + (size_t)b * N_GRID + np);
        float4 r = *(const float4*)(rho + (size_t)b * N_GRID + (4092 - np));
        float up[4] = {f.x + r.w, f.y + r.z, f.z + r.y, f.w + r.x};
        float um[4] = {f.x - r.w, f.y - r.z, f.z - r.y, f.w - r.x};
        __nv_bfloat16 ph[4], pl[4], mh[4], ml[4];
#pragma unroll
        for (int j = 0; j < 4; j++) { split2(up[j], ph[j], pl[j]); split2(um[j], mh[j], ml[j]); }
        ((uint2*)g_uP_hi)[t] = *(uint2*)ph;
        ((uint2*)g_uP_lo)[t] = *(uint2*)pl;
        ((uint2*)g_uM_hi)[t] = *(uint2*)mh;
        ((uint2*)g_uM_lo)[t] = *(uint2*)ml;
    } else if (bx < 4096) {
        int t = (bx - 2048) * 256 + threadIdx.x;
        int g = t >> 18;
        int rem = t & 0x3FFFF;
        int kp = rem >> 11, np = rem & (NH - 1);
        int k = g ? (2 * kp + 1) : (2 * kp + 2);
        float v = cs_val(np, k);
        __nv_bfloat16 h, l;
        split2(v, h, l);
        g_CsF_hi[t] = h; g_CsF_lo[t] = l;
    } else {
        int t = (bx - 4096) * 256 + threadIdx.x;
        int g = t >> 18;
        int rem = t & 0x3FFFF;
        int np = rem >> 7, kp = rem & 127;
        int k = g ? (2 * kp + 1) : (2 * kp + 2);
        float v = cs_val(np, k);
        __nv_bfloat16 h, l;
        split2(v, h, l);
        g_CsT_hi[t] = h; g_CsT_lo[t] = l;
    }
}

// ---------------------------------------------------------------------------
__device__ __forceinline__ void tile_async(uint32_t dst, const __nv_bfloat16* src,
                                           int stride, int tid) {          // 128x64
    const int row = tid >> 2;
    const int c0 = tid & 3;
    const char* s = (const char*)(src + (size_t)row * stride);
#pragma unroll
    for (int i = 0; i < 2; i++) {
        int ch = c0 + i * 4;
        cp16(dst + swz((uint32_t)row * 128 + ch * 16), s + ch * 16);
    }
}
__device__ __forceinline__ void tile_async64(uint32_t dst, const __nv_bfloat16* src,
                                             int stride, int tid) {        // 64x64
    const int row = tid >> 3;
    const int ch = tid & 7;
    cp16(dst + swz((uint32_t)row * 128 + ch * 16), (const char*)(src + (size_t)row * stride) + ch * 16);
}

// ---------------------------------------------------------------------------
// one 64-wide K step; warp tile 32x32; B fetched via paired-k16 ldsm_x4
// ---------------------------------------------------------------------------
template <int ALO, int BLO>
__device__ __forceinline__ void compute_step(uint32_t aB, uint32_t bB, int wm, int wn,
                                             int lane, float acc[2][4][4]) {
    const uint32_t aRow = (uint32_t)(wm * 32 + (lane & 15)) * 128 + ((lane >> 4) << 4);
    // lanes 0-15: k16 sub 0 fragments; lanes 16-31: +32B = k16 sub 1
    const uint32_t bRow = (uint32_t)(wn * 32 + (lane & 7)) * 128 + (((lane >> 3) & 1) << 4)
                          + ((lane >> 4) & 1) * 32;
#pragma unroll
    for (int kp = 0; kp < 2; kp++) {
        const uint32_t kbp = kp * 64;
        uint32_t bH[4][2][2], bL[4][2][2];          // [nj][ksub][frag]
#pragma unroll
        for (int nj = 0; nj < 4; nj++) {
            uint32_t off = swz(bRow + nj * 8 * 128 + kbp);
            ldsm_x4(bH[nj][0][0], bH[nj][0][1], bH[nj][1][0], bH[nj][1][1], bB + off);
            ldsm_x4(bL[nj][0][0], bL[nj][0][1], bL[nj][1][0], bL[nj][1][1], bB + BLO + off);
        }
#pragma unroll
        for (int ks = 0; ks < 2; ks++) {
            const uint32_t kb = kbp + ks * 32;
            uint32_t aH[2][4], aL[2][4];
#pragma unroll
            for (int mi = 0; mi < 2; mi++) {
                uint32_t off = swz(aRow + mi * 16 * 128 + kb);
                ldsm_x4(aH[mi][0], aH[mi][1], aH[mi][2], aH[mi][3], aB + off);
                ldsm_x4(aL[mi][0], aL[mi][1], aL[mi][2], aL[mi][3], aB + ALO + off);
            }
#pragma unroll
            for (int mi = 0; mi < 2; mi++)
#pragma unroll
                for (int nj = 0; nj < 4; nj++)
                    mma_bf16(acc[mi][nj], aH[mi][0], aH[mi][1], aH[mi][2], aH[mi][3],
                             bH[nj][ks][0], bH[nj][ks][1]);
#pragma unroll
            for (int mi = 0; mi < 2; mi++)
#pragma unroll
                for (int nj = 0; nj < 4; nj++)
                    mma_bf16(acc[mi][nj], aH[mi][0], aH[mi][1], aH[mi][2], aH[mi][3],
                             bL[nj][ks][0], bL[nj][ks][1]);
#pragma unroll
            for (int mi = 0; mi < 2; mi++)
#pragma unroll
                for (int nj = 0; nj < 4; nj++)
                    mma_bf16(acc[mi][nj], aL[mi][0], aL[mi][1], aL[mi][2], aL[mi][3],
                             bH[nj][ks][0], bH[nj][ks][1]);
        }
    }
}

// ---------------------------------------------------------------------------
// GEMM1: 3-stage ring, one sync per step. grid (8, 2, SPLITS), block 512.
// ---------------------------------------------------------------------------
#define STG1 65536
#define SMEM1_BYTES (3 * STG1)

__global__ __launch_bounds__(512) void gemm1_hmma(int Brows) {
    extern __shared__ char sm[];
    const uint32_t sb = smem_u32(sm);
    const int tid = threadIdx.x, wid = tid >> 5, lane = tid & 31;
    const int wm = wid & 3, wn = wid >> 2;
    const int mt = blockIdx.x, grp = blockIdx.y, sp = blockIdx.z;
    const int k0 = sp * (NH / SPLITS);
    const int NS = (NH / SPLITS) / 64;               // 4

    float acc[2][4][4];
#pragma unroll
    for (int a = 0; a < 2; a++)
#pragma unroll
        for (int b = 0; b < 4; b++)
#pragma unroll
            for (int c = 0; c < 4; c++) acc[a][b][c] = 0.0f;

    const __nv_bfloat16* aHsrc = (grp ? g_uM_hi : g_uP_hi) + (size_t)(mt * 128) * NH + k0;
    const __nv_bfloat16* aLsrc = (grp ? g_uM_lo : g_uP_lo) + (size_t)(mt * 128) * NH + k0;
    const __nv_bfloat16* bHsrc = g_CsF_hi + (size_t)grp * 128 * NH + k0;
    const __nv_bfloat16* bLsrc = g_CsF_lo + (size_t)grp * 128 * NH + k0;

#define G1FILL(slot, ko)                                          \
    do {                                                          \
        uint32_t st_ = sb + (slot) * STG1;                        \
        tile_async(st_,         aHsrc + (ko), NH, tid);           \
        tile_async(st_ + 16384, aLsrc + (ko), NH, tid);           \
        tile_async(st_ + 32768, bHsrc + (ko), NH, tid);           \
        tile_async(st_ + 49152, bLsrc + (ko), NH, tid);           \
        cp_commit();                                              \
    } while (0)

    G1FILL(0, 0);
    G1FILL(1, 64);
    for (int s = 0; s < NS; s++) {
        if (s + 1 < NS) cp_wait<1>(); else cp_wait<0>();
        __syncthreads();
        if (s + 2 < NS) {
            int slot = (s + 2) % 3;
            G1FILL(slot, (s + 2) * 64);
        }
        uint32_t st = sb + (s % 3) * STG1;
        compute_step<16384, 16384>(st, st + 32768, wm, wn, lane, acc);
    }

    const int g = lane >> 2, tig = lane & 3;
    const int mbase = mt * 128 + wm * 32;
    const int nbase = wn * 32;
#pragma unroll
    for (int mi = 0; mi < 2; mi++)
#pragma unroll
        for (int nj = 0; nj < 4; nj++) {
            int row = mbase + mi * 16 + g;
            int col = nbase + nj * 8 + tig * 2;
            float* p0 = g_part + ((size_t)(grp * SPLITS + sp) * Brows + row) * 128 + col;
            *(float2*)p0             = make_float2(acc[mi][nj][0], acc[mi][nj][1]);
            *(float2*)(p0 + 8 * 128) = make_float2(acc[mi][nj][2], acc[mi][nj][3]);
        }
}

__global__ void reduce_lam_kernel(const float* __restrict__ ms, int Brows) {
    int g = blockIdx.y;
    int idx = blockIdx.x * blockDim.x + threadIdx.x;
    int kp = idx & 127;
    float sum = 0.0f;
#pragma unroll
    for (int s = 0; s < SPLITS; s++)
        sum += g_part[(size_t)(g * SPLITS + s) * Brows * 128 + idx];
    float v = ms[g ? (2 * kp) : (2 * kp + 1)] * sum;
    __nv_bfloat16 h, l;
    split2(v, h, l);
    if (g) { g_Ao_hi[idx] = h; g_Ao_lo[idx] = l; }
    else   { g_Ae_hi[idx] = h; g_Ae_lo[idx] = l; }
}

// ---------------------------------------------------------------------------
// GEMM2 (R8 structure): grid (8, 16), block 512. Warp 32x16 dual e/o tiles.
// A resident 128KB; B per 64-col half 64KB; register e±o epilogue.
// B loads now paired-k16 ldsm_x4.
// ---------------------------------------------------------------------------
#define B_BASE 131072
#define SMEM2_BYTES 196608

__device__ __forceinline__ void fill_B2(uint32_t sb, int nt, int h, int tid) {
#pragma unroll
    for (int kc = 0; kc < 2; kc++) {
        size_t be = ((size_t)(nt * 128 + h * 64)) * 128 + kc * 64;
        size_t bo = (size_t)NH * 128 + be;
        tile_async64(sb + B_BASE +         kc * 8192, g_CsT_hi + be, 128, tid);
        tile_async64(sb + B_BASE + 16384 + kc * 8192, g_CsT_lo + be, 128, tid);
        tile_async64(sb + B_BASE + 32768 + kc * 8192, g_CsT_hi + bo, 128, tid);
        tile_async64(sb + B_BASE + 49152 + kc * 8192, g_CsT_lo + bo, 128, tid);
    }
    cp_commit();
}

__global__ __launch_bounds__(512) void gemm2_hmma(float* __restrict__ phi) {
    extern __shared__ char sm[];
    const uint32_t sb = smem_u32(sm);
    const int tid = threadIdx.x, wid = tid >> 5, lane = tid & 31;
    const int wm = wid & 3, wn = wid >> 2;
    const int mt = blockIdx.x, nt = blockIdx.y;

    // A resident fill (8 tiles = 128KB): region(eo,op)*32768 + kc*16384
    {
        const size_t aoff = (size_t)(mt * 128) * 128;
#pragma unroll
        for (int kc = 0; kc < 2; kc++) {
            tile_async(sb +          kc * 16384, g_Ae_hi + aoff + kc * 64, 128, tid);
            tile_async(sb + 32768 +  kc * 16384, g_Ae_lo + aoff + kc * 64, 128, tid);
            tile_async(sb + 65536 +  kc * 16384, g_Ao_hi + aoff + kc * 64, 128, tid);
            tile_async(sb + 98304 +  kc * 16384, g_Ao_lo + aoff + kc * 64, 128, tid);
        }
        cp_commit();
    }
    fill_B2(sb, nt, 0, tid);

    const uint32_t aRow = (uint32_t)(wm * 32 + (lane & 15)) * 128 + ((lane >> 4) << 4);
    const uint32_t bRow = (uint32_t)(wn * 16 + (lane & 7)) * 128 + (((lane >> 3) & 1) << 4)
                          + ((lane >> 4) & 1) * 32;
    const int g = lane >> 2, tig = lane & 3;

    for (int h = 0; h < 2; h++) {
        float acc[2][2][2][4];                       // [eo][mi][nj][4]
#pragma unroll
        for (int e = 0; e < 2; e++)
#pragma unroll
            for (int a = 0; a < 2; a++)
#pragma unroll
                for (int b = 0; b < 2; b++)
#pragma unroll
                    for (int c = 0; c < 4; c++) acc[e][a][b][c] = 0.0f;

        cp_wait<0>();
        __syncthreads();

#pragma unroll
        for (int kc = 0; kc < 2; kc++) {
#pragma unroll
            for (int kp = 0; kp < 2; kp++) {
                const uint32_t kbp = kp * 64;
#pragma unroll
                for (int eo = 0; eo < 2; eo++) {
                    uint32_t aBase = sb + eo * 65536u + kc * 16384u;
                    uint32_t bBase = sb + B_BASE + eo * 32768u + kc * 8192u;
                    uint32_t bH[2][2][2], bL[2][2][2];
#pragma unroll
                    for (int nj = 0; nj < 2; nj++) {
                        uint32_t off = swz(bRow + nj * 8 * 128 + kbp);
                        ldsm_x4(bH[nj][0][0], bH[nj][0][1], bH[nj][1][0], bH[nj][1][1], bBase + off);
                        ldsm_x4(bL[nj][0][0], bL[nj][0][1], bL[nj][1][0], bL[nj][1][1],
                                bBase + 16384u + off);
                    }
#pragma unroll
                    for (int ks = 0; ks < 2; ks++) {
                        const uint32_t kb = kbp + ks * 32;
                        uint32_t aH[2][4], aL[2][4];
#pragma unroll
                        for (int mi = 0; mi < 2; mi++) {
                            uint32_t off = swz(aRow + mi * 16 * 128 + kb);
                            ldsm_x4(aH[mi][0], aH[mi][1], aH[mi][2], aH[mi][3], aBase + off);
                            ldsm_x4(aL[mi][0], aL[mi][1], aL[mi][2], aL[mi][3], aBase + 32768u + off);
                        }
#pragma unroll
                        for (int mi = 0; mi < 2; mi++)
#pragma unroll
                            for (int nj = 0; nj < 2; nj++)
                                mma_bf16(acc[eo][mi][nj], aH[mi][0], aH[mi][1], aH[mi][2], aH[mi][3],
                                         bH[nj][ks][0], bH[nj][ks][1]);
#pragma unroll
                        for (int mi = 0; mi < 2; mi++)
#pragma unroll
                            for (int nj = 0; nj < 2; nj++)
                                mma_bf16(acc[eo][mi][nj], aH[mi][0], aH[mi][1], aH[mi][2], aH[mi][3],
                                         bL[nj][ks][0], bL[nj][ks][1]);
#pragma unroll
                        for (int mi = 0; mi < 2; mi++)
#pragma unroll
                            for (int nj = 0; nj < 2; nj++)
                                mma_bf16(acc[eo][mi][nj], aL[mi][0], aL[mi][1], aL[mi][2], aL[mi][3],
                                         bH[nj][ks][0], bH[nj][ks][1]);
                    }
                }
            }
        }
        __syncthreads();                 // all warps done reading B(h)
        if (h == 0) fill_B2(sb, nt, 1, tid);

        // register epilogue: phi[n'] = e + o ; phi[4095-n'] = e - o
#pragma unroll
        for (int mi = 0; mi < 2; mi++)
#pragma unroll
            for (int nj = 0; nj < 2; nj++) {
#pragma unroll
                for (int half = 0; half < 2; half++) {
                    int row = mt * 128 + wm * 32 + mi * 16 + half * 8 + g;
                    int c = nt * 128 + h * 64 + wn * 16 + nj * 8 + tig * 2;
                    float e0 = acc[0][mi][nj][half * 2];
                    float e1 = acc[0][mi][nj][half * 2 + 1];
                    float o0 = acc[1][mi][nj][half * 2];
                    float o1 = acc[1][mi][nj][half * 2 + 1];
                    float* rowp = phi + (size_t)row * N_GRID;
                    *(float2*)(rowp + c) = make_float2(e0 + o0, e1 + o1);
                    *(float2*)(rowp + (4094 - c)) = make_float2(e1 - o1, e0 - o0);
                }
            }
    }
}

// ---------------------------------------------------------------------------
extern "C" void kernel_launch(void* const* d_in, const int* in_sizes, int n_in,
                              void* d_out, int out_size) {
    const float* rho = (const float*)d_in[0];
    const float* ms  = (const float*)d_in[1];
    float* phi = (float*)d_out;
    const int Brows = in_sizes[0] / N_GRID;

    cudaFuncSetAttribute(gemm1_hmma, cudaFuncAttributeMaxDynamicSharedMemorySize, SMEM1_BYTES);
    cudaFuncSetAttribute(gemm2_hmma, cudaFuncAttributeMaxDynamicSharedMemorySize, SMEM2_BYTES);

    prep_kernel<<<6144, 256>>>(rho);

    dim3 g1(Brows / 128, 2, SPLITS);
    gemm1_hmma<<<g1, 512, SMEM1_BYTES>>>(Brows);

    dim3 gr((Brows * 128) / 256, 2);
    reduce_lam_kernel<<<gr, 256>>>(ms, Brows);

    dim3 g2(Brows / 128, NH / 128);
    gemm2_hmma<<<g2, 512, SMEM2_BYTES>>>(phi);
}

// round 11
// speedup vs baseline: 1.3546x; 1.2108x over previous
#include <cuda_runtime.h>
#include <cuda_fp16.h>
#include <math.h>
#include <stdint.h>

#define N_GRID 4096
#define NH     2048
#define SPLITS 8
#define MAXB   1024

// ---------------- device scratch ----------------
__device__ __half g_uP_h [MAXB * NH];        // folded rho (fp16 hi only)
__device__ __half g_uM_h [MAXB * NH];
__device__ __half g_CsF_h[2 * 128 * NH];     // unscaled cos, [g][k'][n']
__device__ __half g_CsF_l[2 * 128 * NH];
__device__ __half g_CsT_h[2 * NH * 128];     // unscaled cos, [g][n'][k']
__device__ __half g_CsT_l[2 * NH * 128];
__device__ float  g_part [16 * MAXB * 128];
__device__ __half g_Ae_h [MAXB * 128];       // 2*ms-scaled coeffs (fp16)
__device__ __half g_Ao_h [MAXB * 128];

// ---------------- helpers ----------------
__device__ __forceinline__ uint32_t smem_u32(const void* p) {
    uint32_t a;
    asm("{ .reg .u64 t; cvta.to.shared.u64 t, %1; cvt.u32.u64 %0, t; }" : "=r"(a) : "l"(p));
    return a;
}
__device__ __forceinline__ uint32_t swz(uint32_t off) { return off ^ ((off >> 3) & 0x70); }

__device__ __forceinline__ void cp16(uint32_t dst, const void* src) {
    asm volatile("cp.async.cg.shared.global [%0], [%1], 16;" :: "r"(dst), "l"(src));
}
__device__ __forceinline__ void cp_commit() {
    asm volatile("cp.async.commit_group;" ::: "memory");
}
template <int N>
__device__ __forceinline__ void cp_wait() {
    asm volatile("cp.async.wait_group %0;" :: "n"(N) : "memory");
}

__device__ __forceinline__ void ldsm_x4(uint32_t& r0, uint32_t& r1, uint32_t& r2, uint32_t& r3,
                                        uint32_t addr) {
    asm volatile("ldmatrix.sync.aligned.m8n8.x4.shared.b16 {%0,%1,%2,%3}, [%4];"
                 : "=r"(r0), "=r"(r1), "=r"(r2), "=r"(r3) : "r"(addr));
}
__device__ __forceinline__ void mma_f16(float* c, uint32_t a0, uint32_t a1, uint32_t a2,
                                        uint32_t a3, uint32_t b0, uint32_t b1) {
    asm volatile("mma.sync.aligned.m16n8k16.row.col.f32.f16.f16.f32 "
                 "{%0,%1,%2,%3}, {%4,%5,%6,%7}, {%8,%9}, {%0,%1,%2,%3};"
                 : "+f"(c[0]), "+f"(c[1]), "+f"(c[2]), "+f"(c[3])
                 : "r"(a0), "r"(a1), "r"(a2), "r"(a3), "r"(b0), "r"(b1));
}

union H4 { __half h[4]; uint2 v; };

__device__ __forceinline__ void split2h(float v, __half& h, __half& l) {
    h = __float2half(v);
    l = __float2half(v - __half2float(h));
}

// ---------------------------------------------------------------------------
__device__ __forceinline__ float cos_acc(float x) {
    const float INV_PIO2 = 0.6366197723675814f;
    float qf = rintf(x * INV_PIO2);
    int   iq = (int)qf;
    const float HI = 1.57079637050628662109375f;
    const float MD = -4.3711388286737929e-08f;
    const float LO = -1.7151245100059657e-15f;
    float r = fmaf(-qf, HI, x);
    r = fmaf(-qf, MD, r);
    r = fmaf(-qf, LO, r);
    float r2 = r * r;
    float pc = fmaf(r2,  2.4390448796e-05f, -1.3886763775e-03f);
    pc = fmaf(r2, pc,  4.1666623323e-02f);
    pc = fmaf(r2, pc, -4.9999999725e-01f);
    pc = fmaf(r2, pc,  1.0f);
    float ps = fmaf(r2,  2.7183114939e-06f, -1.9839334836e-04f);
    ps = fmaf(r2, ps,  8.3333293859e-03f);
    ps = fmaf(r2, ps, -1.6666666642e-01f);
    ps = r * fmaf(r2, ps, 1.0f);
    int n = iq & 3;
    float v = (n & 1) ? ps : pc;
    if (n == 1 || n == 2) v = -v;
    return v;
}

__device__ __forceinline__ float cs_raw(int n, int k) {   // unscaled cos
    const float PI_F = 3.1415927410125732421875f;
    float t1 = PI_F * (float)(2 * n + 1);
    float theta = (t1 * (float)k) * (1.0f / 8192.0f);
    return cos_acc(theta);
}

// ---------------------------------------------------------------------------
// prep: fold rho -> u fp16 (hi only); build unscaled Cs tables (fp16 hi/lo)
// ---------------------------------------------------------------------------
__global__ void prep_kernel(const float* __restrict__ rho) {
    int bx = blockIdx.x;
    if (bx < 2048) {
        int t = bx * 256 + threadIdx.x;      // 4 n' each
        int b = t >> 9;
        int np = (t & 511) * 4;
        float4 f = *(const float4*)(rho + (size_t)b * N_GRID + np);
        float4 r = *(const float4*)(rho + (size_t)b * N_GRID + (4092 - np));
        H4 p, m;
        p.h[0] = __float2half(f.x + r.w); p.h[1] = __float2half(f.y + r.z);
        p.h[2] = __float2half(f.z + r.y); p.h[3] = __float2half(f.w + r.x);
        m.h[0] = __float2half(f.x - r.w); m.h[1] = __float2half(f.y - r.z);
        m.h[2] = __float2half(f.z - r.y); m.h[3] = __float2half(f.w - r.x);
        ((uint2*)g_uP_h)[t] = p.v;
        ((uint2*)g_uM_h)[t] = m.v;
    } else if (bx < 4096) {
        int t = (bx - 2048) * 256 + threadIdx.x;   // [g][k'][n']
        int g = t >> 18;
        int rem = t & 0x3FFFF;
        int kp = rem >> 11, np = rem & (NH - 1);
        int k = g ? (2 * kp + 1) : (2 * kp + 2);
        float v = cs_raw(np, k);
        __half h, l;
        split2h(v, h, l);
        g_CsF_h[t] = h; g_CsF_l[t] = l;
    } else {
        int t = (bx - 4096) * 256 + threadIdx.x;   // [g][n'][k']
        int g = t >> 18;
        int rem = t & 0x3FFFF;
        int np = rem >> 7, kp = rem & 127;
        int k = g ? (2 * kp + 1) : (2 * kp + 2);
        float v = cs_raw(np, k);
        __half h, l;
        split2h(v, h, l);
        g_CsT_h[t] = h; g_CsT_l[t] = l;
    }
}

// ---------------------------------------------------------------------------
__device__ __forceinline__ void tile_async(uint32_t dst, const __half* src,
                                           int stride, int tid) {          // 128x64
    const int row = tid >> 2;
    const int c0 = tid & 3;
    const char* s = (const char*)(src + (size_t)row * stride);
#pragma unroll
    for (int i = 0; i < 2; i++) {
        int ch = c0 + i * 4;
        cp16(dst + swz((uint32_t)row * 128 + ch * 16), s + ch * 16);
    }
}
__device__ __forceinline__ void tile_async64(uint32_t dst, const __half* src,
                                             int stride, int tid) {        // 64x64
    const int row = tid >> 3;
    const int ch = tid & 7;
    cp16(dst + swz((uint32_t)row * 128 + ch * 16), (const char*)(src + (size_t)row * stride) + ch * 16);
}

// ---------------------------------------------------------------------------
// GEMM1: one 64-wide K step; warp tile 32x32; terms Ah*Bh + Ah*Bl
// ---------------------------------------------------------------------------
__device__ __forceinline__ void g1_step(uint32_t aB, uint32_t bB, int wm, int wn,
                                        int lane, float acc[2][4][4]) {
    const uint32_t aRow = (uint32_t)(wm * 32 + (lane & 15)) * 128 + ((lane >> 4) << 4);
    const uint32_t bRow = (uint32_t)(wn * 32 + (lane & 7)) * 128 + (((lane >> 3) & 1) << 4)
                          + ((lane >> 4) & 1) * 32;
#pragma unroll
    for (int kp = 0; kp < 2; kp++) {
        const uint32_t kbp = kp * 64;
        uint32_t bH[4][2][2], bL[4][2][2];
#pragma unroll
        for (int nj = 0; nj < 4; nj++) {
            uint32_t off = swz(bRow + nj * 8 * 128 + kbp);
            ldsm_x4(bH[nj][0][0], bH[nj][0][1], bH[nj][1][0], bH[nj][1][1], bB + off);
            ldsm_x4(bL[nj][0][0], bL[nj][0][1], bL[nj][1][0], bL[nj][1][1], bB + 16384u + off);
        }
#pragma unroll
        for (int ks = 0; ks < 2; ks++) {
            const uint32_t kb = kbp + ks * 32;
            uint32_t aH[2][4];
#pragma unroll
            for (int mi = 0; mi < 2; mi++) {
                uint32_t off = swz(aRow + mi * 16 * 128 + kb);
                ldsm_x4(aH[mi][0], aH[mi][1], aH[mi][2], aH[mi][3], aB + off);
            }
#pragma unroll
            for (int mi = 0; mi < 2; mi++)
#pragma unroll
                for (int nj = 0; nj < 4; nj++)
                    mma_f16(acc[mi][nj], aH[mi][0], aH[mi][1], aH[mi][2], aH[mi][3],
                            bH[nj][ks][0], bH[nj][ks][1]);
#pragma unroll
            for (int mi = 0; mi < 2; mi++)
#pragma unroll
                for (int nj = 0; nj < 4; nj++)
                    mma_f16(acc[mi][nj], aH[mi][0], aH[mi][1], aH[mi][2], aH[mi][3],
                            bL[nj][ks][0], bL[nj][ks][1]);
        }
    }
}

// ---------------------------------------------------------------------------
// GEMM1: 3-stage ring (48KB/stage: A 0, Bh 16K, Bl 32K). grid (8,2,8), 512 thr.
// ---------------------------------------------------------------------------
#define STG1 49152
#define SMEM1_BYTES (3 * STG1)

__global__ __launch_bounds__(512) void gemm1_hmma(int Brows) {
    extern __shared__ char sm[];
    const uint32_t sb = smem_u32(sm);
    const int tid = threadIdx.x, wid = tid >> 5, lane = tid & 31;
    const int wm = wid & 3, wn = wid >> 2;
    const int mt = blockIdx.x, grp = blockIdx.y, sp = blockIdx.z;
    const int k0 = sp * (NH / SPLITS);
    const int NS = (NH / SPLITS) / 64;               // 4

    float acc[2][4][4];
#pragma unroll
    for (int a = 0; a < 2; a++)
#pragma unroll
        for (int b = 0; b < 4; b++)
#pragma unroll
            for (int c = 0; c < 4; c++) acc[a][b][c] = 0.0f;

    const __half* aHsrc = (grp ? g_uM_h : g_uP_h) + (size_t)(mt * 128) * NH + k0;
    const __half* bHsrc = g_CsF_h + (size_t)grp * 128 * NH + k0;
    const __half* bLsrc = g_CsF_l + (size_t)grp * 128 * NH + k0;

#define G1FILL(slot, ko)                                          \
    do {                                                          \
        uint32_t st_ = sb + (slot) * STG1;                        \
        tile_async(st_,         aHsrc + (ko), NH, tid);           \
        tile_async(st_ + 16384, bHsrc + (ko), NH, tid);           \
        tile_async(st_ + 32768, bLsrc + (ko), NH, tid);           \
        cp_commit();                                              \
    } while (0)

    G1FILL(0, 0);
    G1FILL(1, 64);
    for (int s = 0; s < NS; s++) {
        if (s + 1 < NS) cp_wait<1>(); else cp_wait<0>();
        __syncthreads();
        if (s + 2 < NS) {
            int slot = (s + 2) % 3;
            G1FILL(slot, (s + 2) * 64);
        }
        uint32_t st = sb + (s % 3) * STG1;
        g1_step(st, st + 16384, wm, wn, lane, acc);
    }

    const int g = lane >> 2, tig = lane & 3;
    const int mbase = mt * 128 + wm * 32;
    const int nbase = wn * 32;
#pragma unroll
    for (int mi = 0; mi < 2; mi++)
#pragma unroll
        for (int nj = 0; nj < 4; nj++) {
            int row = mbase + mi * 16 + g;
            int col = nbase + nj * 8 + tig * 2;
            float* p0 = g_part + ((size_t)(grp * SPLITS + sp) * Brows + row) * 128 + col;
            *(float2*)p0             = make_float2(acc[mi][nj][0], acc[mi][nj][1]);
            *(float2*)(p0 + 8 * 128) = make_float2(acc[mi][nj][2], acc[mi][nj][3]);
        }
}

// reduce splits + lam scale; SCALE^2 * 4096 = 2.0 exactly folded in here,
// epilogue divides by 4096 (exact power of 2).
__global__ void reduce_lam_kernel(const float* __restrict__ ms, int Brows) {
    int g = blockIdx.y;
    int idx = blockIdx.x * blockDim.x + threadIdx.x;
    int kp = idx & 127;
    float sum = 0.0f;
#pragma unroll
    for (int s = 0; s < SPLITS; s++)
        sum += g_part[(size_t)(g * SPLITS + s) * Brows * 128 + idx];
    float v = 2.0f * ms[g ? (2 * kp) : (2 * kp + 1)] * sum;
    if (g) g_Ao_h[idx] = __float2half(v);
    else   g_Ae_h[idx] = __float2half(v);
}

// ---------------------------------------------------------------------------
// GEMM2: grid (8, 16), block 512. A resident 64KB (eo*32K + kc*16K),
// B resident BOTH halves 128KB (65536 + h*64K + eo*32K + op*16K + kc*8K).
// Warp 32x16 dual e/o tiles; register e±o epilogue (x 1/4096).
// Only 2 __syncthreads total.
// ---------------------------------------------------------------------------
#define B2_BASE 65536
#define SMEM2_BYTES 196608

__global__ __launch_bounds__(512) void gemm2_hmma(float* __restrict__ phi) {
    extern __shared__ char sm[];
    const uint32_t sb = smem_u32(sm);
    const int tid = threadIdx.x, wid = tid >> 5, lane = tid & 31;
    const int wm = wid & 3, wn = wid >> 2;
    const int mt = blockIdx.x, nt = blockIdx.y;
    const float OSC = 1.0f / 4096.0f;

    // A resident (4 tiles = 64KB) + B(h0) (8 tiles = 64KB) -> group 0
    {
        const size_t aoff = (size_t)(mt * 128) * 128;
#pragma unroll
        for (int kc = 0; kc < 2; kc++) {
            tile_async(sb +          kc * 16384, g_Ae_h + aoff + kc * 64, 128, tid);
            tile_async(sb + 32768 +  kc * 16384, g_Ao_h + aoff + kc * 64, 128, tid);
        }
#pragma unroll
        for (int eo = 0; eo < 2; eo++)
#pragma unroll
            for (int kc = 0; kc < 2; kc++) {
                size_t boff = (size_t)eo * NH * 128 + (size_t)(nt * 128) * 128 + kc * 64;
                uint32_t bb = sb + B2_BASE + eo * 32768u + kc * 8192u;
                tile_async64(bb,          g_CsT_h + boff, 128, tid);
                tile_async64(bb + 16384u, g_CsT_l + boff, 128, tid);
            }
        cp_commit();
        // B(h1) -> group 1
#pragma unroll
        for (int eo = 0; eo < 2; eo++)
#pragma unroll
            for (int kc = 0; kc < 2; kc++) {
                size_t boff = (size_t)eo * NH * 128 + (size_t)(nt * 128 + 64) * 128 + kc * 64;
                uint32_t bb = sb + B2_BASE + 65536u + eo * 32768u + kc * 8192u;
                tile_async64(bb,          g_CsT_h + boff, 128, tid);
                tile_async64(bb + 16384u, g_CsT_l + boff, 128, tid);
            }
        cp_commit();
    }

    const uint32_t aRow = (uint32_t)(wm * 32 + (lane & 15)) * 128 + ((lane >> 4) << 4);
    const uint32_t bRow = (uint32_t)(wn * 16 + (lane & 7)) * 128 + (((lane >> 3) & 1) << 4)
                          + ((lane >> 4) & 1) * 32;
    const int g = lane >> 2, tig = lane & 3;

    for (int h = 0; h < 2; h++) {
        if (h == 0) cp_wait<1>(); else cp_wait<0>();
        __syncthreads();

        float acc[2][2][2][4];                       // [eo][mi][nj][4]
#pragma unroll
        for (int e = 0; e < 2; e++)
#pragma unroll
            for (int a = 0; a < 2; a++)
#pragma unroll
                for (int b = 0; b < 2; b++)
#pragma unroll
                    for (int c = 0; c < 4; c++) acc[e][a][b][c] = 0.0f;

#pragma unroll
        for (int kc = 0; kc < 2; kc++) {
#pragma unroll
            for (int kp = 0; kp < 2; kp++) {
                const uint32_t kbp = kp * 64;
#pragma unroll
                for (int eo = 0; eo < 2; eo++) {
                    uint32_t aBase = sb + eo * 32768u + kc * 16384u;
                    uint32_t bBase = sb + B2_BASE + (uint32_t)h * 65536u + eo * 32768u + kc * 8192u;
                    uint32_t bH[2][2][2], bL[2][2][2];
#pragma unroll
                    for (int nj = 0; nj < 2; nj++) {
                        uint32_t off = swz(bRow + nj * 8 * 128 + kbp);
                        ldsm_x4(bH[nj][0][0], bH[nj][0][1], bH[nj][1][0], bH[nj][1][1], bBase + off);
                        ldsm_x4(bL[nj][0][0], bL[nj][0][1], bL[nj][1][0], bL[nj][1][1],
                                bBase + 16384u + off);
                    }
#pragma unroll
                    for (int ks = 0; ks < 2; ks++) {
                        const uint32_t kb = kbp + ks * 32;
                        uint32_t aH[2][4];
#pragma unroll
                        for (int mi = 0; mi < 2; mi++) {
                            uint32_t off = swz(aRow + mi * 16 * 128 + kb);
                            ldsm_x4(aH[mi][0], aH[mi][1], aH[mi][2], aH[mi][3], aBase + off);
                        }
#pragma unroll
                        for (int mi = 0; mi < 2; mi++)
#pragma unroll
                            for (int nj = 0; nj < 2; nj++)
                                mma_f16(acc[eo][mi][nj], aH[mi][0], aH[mi][1], aH[mi][2], aH[mi][3],
                                        bH[nj][ks][0], bH[nj][ks][1]);
#pragma unroll
                        for (int mi = 0; mi < 2; mi++)
#pragma unroll
                            for (int nj = 0; nj < 2; nj++)
                                mma_f16(acc[eo][mi][nj], aH[mi][0], aH[mi][1], aH[mi][2], aH[mi][3],
                                        bL[nj][ks][0], bL[nj][ks][1]);
                    }
                }
            }
        }

        // register epilogue: phi[n'] = (e+o)/4096 ; phi[4095-n'] = (e-o)/4096
#pragma unroll
        for (int mi = 0; mi < 2; mi++)
#pragma unroll
            for (int nj = 0; nj < 2; nj++) {
#pragma unroll
                for (int half = 0; half < 2; half++) {
                    int row = mt * 128 + wm * 32 + mi * 16 + half * 8 + g;
                    int c = nt * 128 + h * 64 + wn * 16 + nj * 8 + tig * 2;
                    float e0 = acc[0][mi][nj][half * 2];
                    float e1 = acc[0][mi][nj][half * 2 + 1];
                    float o0 = acc[1][mi][nj][half * 2];
                    float o1 = acc[1][mi][nj][half * 2 + 1];
                    float* rowp = phi + (size_t)row * N_GRID;
                    *(float2*)(rowp + c) = make_float2((e0 + o0) * OSC, (e1 + o1) * OSC);
                    *(float2*)(rowp + (4094 - c)) = make_float2((e1 - o1) * OSC, (e0 - o0) * OSC);
                }
            }
    }
}

// ---------------------------------------------------------------------------
extern "C" void kernel_launch(void* const* d_in, const int* in_sizes, int n_in,
                              void* d_out, int out_size) {
    const float* rho = (const float*)d_in[0];
    const float* ms  = (const float*)d_in[1];
    float* phi = (float*)d_out;
    const int Brows = in_sizes[0] / N_GRID;

    cudaFuncSetAttribute(gemm1_hmma, cudaFuncAttributeMaxDynamicSharedMemorySize, SMEM1_BYTES);
    cudaFuncSetAttribute(gemm2_hmma, cudaFuncAttributeMaxDynamicSharedMemorySize, SMEM2_BYTES);

    prep_kernel<<<6144, 256>>>(rho);

    dim3 g1(Brows / 128, 2, SPLITS);
    gemm1_hmma<<<g1, 512, SMEM1_BYTES>>>(Brows);

    dim3 gr((Brows * 128) / 256, 2);
    reduce_lam_kernel<<<gr, 256>>>(ms, Brows);

    dim3 g2(Brows / 128, NH / 128);
    gemm2_hmma<<<g2, 512, SMEM2_BYTES>>>(phi);
}

// round 12
// speedup vs baseline: 1.5740x; 1.1620x over previous
#include <cuda_runtime.h>
#include <cuda_fp16.h>
#include <math.h>
#include <stdint.h>

#define N_GRID 4096
#define NH     2048
#define SPLITS 8
#define MAXB   1024

// ---------------- device scratch ----------------
__device__ __half g_uP_h [MAXB * NH];        // folded rho (fp16)
__device__ __half g_uM_h [MAXB * NH];
__device__ __half g_CsF_h[2 * 128 * NH];     // unscaled cos, [g][k'][n']
__device__ __half g_CsT_h[2 * NH * 128];     // unscaled cos, [g][n'][k']
__device__ float  g_part [16 * MAXB * 128];
__device__ __half g_Ae_h [MAXB * 128];       // 2*ms-scaled coeffs (fp16)
__device__ __half g_Ao_h [MAXB * 128];

// ---------------- helpers ----------------
__device__ __forceinline__ uint32_t smem_u32(const void* p) {
    uint32_t a;
    asm("{ .reg .u64 t; cvta.to.shared.u64 t, %1; cvt.u32.u64 %0, t; }" : "=r"(a) : "l"(p));
    return a;
}
__device__ __forceinline__ uint32_t swz(uint32_t off) { return off ^ ((off >> 3) & 0x70); }

__device__ __forceinline__ void cp16(uint32_t dst, const void* src) {
    asm volatile("cp.async.cg.shared.global [%0], [%1], 16;" :: "r"(dst), "l"(src));
}
__device__ __forceinline__ void cp_commit() {
    asm volatile("cp.async.commit_group;" ::: "memory");
}
template <int N>
__device__ __forceinline__ void cp_wait() {
    asm volatile("cp.async.wait_group %0;" :: "n"(N) : "memory");
}

__device__ __forceinline__ void ldsm_x4(uint32_t& r0, uint32_t& r1, uint32_t& r2, uint32_t& r3,
                                        uint32_t addr) {
    asm volatile("ldmatrix.sync.aligned.m8n8.x4.shared.b16 {%0,%1,%2,%3}, [%4];"
                 : "=r"(r0), "=r"(r1), "=r"(r2), "=r"(r3) : "r"(addr));
}
__device__ __forceinline__ void mma_f16(float* c, uint32_t a0, uint32_t a1, uint32_t a2,
                                        uint32_t a3, uint32_t b0, uint32_t b1) {
    asm volatile("mma.sync.aligned.m16n8k16.row.col.f32.f16.f16.f32 "
                 "{%0,%1,%2,%3}, {%4,%5,%6,%7}, {%8,%9}, {%0,%1,%2,%3};"
                 : "+f"(c[0]), "+f"(c[1]), "+f"(c[2]), "+f"(c[3])
                 : "r"(a0), "r"(a1), "r"(a2), "r"(a3), "r"(b0), "r"(b1));
}

union H4 { __half h[4]; uint2 v; };

// ---------------------------------------------------------------------------
__device__ __forceinline__ float cos_acc(float x) {
    const float INV_PIO2 = 0.6366197723675814f;
    float qf = rintf(x * INV_PIO2);
    int   iq = (int)qf;
    const float HI = 1.57079637050628662109375f;
    const float MD = -4.3711388286737929e-08f;
    const float LO = -1.7151245100059657e-15f;
    float r = fmaf(-qf, HI, x);
    r = fmaf(-qf, MD, r);
    r = fmaf(-qf, LO, r);
    float r2 = r * r;
    float pc = fmaf(r2,  2.4390448796e-05f, -1.3886763775e-03f);
    pc = fmaf(r2, pc,  4.1666623323e-02f);
    pc = fmaf(r2, pc, -4.9999999725e-01f);
    pc = fmaf(r2, pc,  1.0f);
    float ps = fmaf(r2,  2.7183114939e-06f, -1.9839334836e-04f);
    ps = fmaf(r2, ps,  8.3333293859e-03f);
    ps = fmaf(r2, ps, -1.6666666642e-01f);
    ps = r * fmaf(r2, ps, 1.0f);
    int n = iq & 3;
    float v = (n & 1) ? ps : pc;
    if (n == 1 || n == 2) v = -v;
    return v;
}

__device__ __forceinline__ float cs_raw(int n, int k) {   // unscaled cos
    const float PI_F = 3.1415927410125732421875f;
    float t1 = PI_F * (float)(2 * n + 1);
    float theta = (t1 * (float)k) * (1.0f / 8192.0f);
    return cos_acc(theta);
}

// ---------------------------------------------------------------------------
// prep: fold rho -> u fp16 ; build unscaled Cs tables (fp16, hi only)
// ---------------------------------------------------------------------------
__global__ void prep_kernel(const float* __restrict__ rho) {
    int bx = blockIdx.x;
    if (bx < 2048) {
        int t = bx * 256 + threadIdx.x;      // 4 n' each
        int b = t >> 9;
        int np = (t & 511) * 4;
        float4 f = *(const float4*)(rho + (size_t)b * N_GRID + np);
        float4 r = *(const float4*)(rho + (size_t)b * N_GRID + (4092 - np));
        H4 p, m;
        p.h[0] = __float2half(f.x + r.w); p.h[1] = __float2half(f.y + r.z);
        p.h[2] = __float2half(f.z + r.y); p.h[3] = __float2half(f.w + r.x);
        m.h[0] = __float2half(f.x - r.w); m.h[1] = __float2half(f.y - r.z);
        m.h[2] = __float2half(f.z - r.y); m.h[3] = __float2half(f.w - r.x);
        ((uint2*)g_uP_h)[t] = p.v;
        ((uint2*)g_uM_h)[t] = m.v;
    } else if (bx < 4096) {
        int t = (bx - 2048) * 256 + threadIdx.x;   // [g][k'][n']
        int g = t >> 18;
        int rem = t & 0x3FFFF;
        int kp = rem >> 11, np = rem & (NH - 1);
        int k = g ? (2 * kp + 1) : (2 * kp + 2);
        g_CsF_h[t] = __float2half(cs_raw(np, k));
    } else {
        int t = (bx - 4096) * 256 + threadIdx.x;   // [g][n'][k']
        int g = t >> 18;
        int rem = t & 0x3FFFF;
        int np = rem >> 7, kp = rem & 127;
        int k = g ? (2 * kp + 1) : (2 * kp + 2);
        g_CsT_h[t] = __float2half(cs_raw(np, k));
    }
}

// ---------------------------------------------------------------------------
__device__ __forceinline__ void tile_async(uint32_t dst, const __half* src,
                                           int stride, int tid) {          // 128x64
    const int row = tid >> 2;
    const int c0 = tid & 3;
    const char* s = (const char*)(src + (size_t)row * stride);
#pragma unroll
    for (int i = 0; i < 2; i++) {
        int ch = c0 + i * 4;
        cp16(dst + swz((uint32_t)row * 128 + ch * 16), s + ch * 16);
    }
}

// ---------------------------------------------------------------------------
// single-term 64-wide K step; warp tile 32x32 (mi=2, nj=4); paired-k16 B
// ---------------------------------------------------------------------------
__device__ __forceinline__ void g1_step(uint32_t aB, uint32_t bB, uint32_t aRow,
                                        uint32_t bRow, float acc[2][4][4]) {
#pragma unroll
    for (int kp = 0; kp < 2; kp++) {
        const uint32_t kbp = kp * 64;
        uint32_t bH[4][2][2];
#pragma unroll
        for (int nj = 0; nj < 4; nj++) {
            uint32_t off = swz(bRow + nj * 8 * 128 + kbp);
            ldsm_x4(bH[nj][0][0], bH[nj][0][1], bH[nj][1][0], bH[nj][1][1], bB + off);
        }
#pragma unroll
        for (int ks = 0; ks < 2; ks++) {
            const uint32_t kb = kbp + ks * 32;
            uint32_t aH[2][4];
#pragma unroll
            for (int mi = 0; mi < 2; mi++) {
                uint32_t off = swz(aRow + mi * 16 * 128 + kb);
                ldsm_x4(aH[mi][0], aH[mi][1], aH[mi][2], aH[mi][3], aB + off);
            }
#pragma unroll
            for (int mi = 0; mi < 2; mi++)
#pragma unroll
                for (int nj = 0; nj < 4; nj++)
                    mma_f16(acc[mi][nj], aH[mi][0], aH[mi][1], aH[mi][2], aH[mi][3],
                            bH[nj][ks][0], bH[nj][ks][1]);
        }
    }
}

// ---------------------------------------------------------------------------
// GEMM1: single-term. 3-stage ring (32KB/stage: A 0, B 16K). grid (8,2,8).
// ---------------------------------------------------------------------------
#define STG1 32768
#define SMEM1_BYTES (3 * STG1)

__global__ __launch_bounds__(512) void gemm1_hmma(int Brows) {
    extern __shared__ char sm[];
    const uint32_t sb = smem_u32(sm);
    const int tid = threadIdx.x, wid = tid >> 5, lane = tid & 31;
    const int wm = wid & 3, wn = wid >> 2;
    const int mt = blockIdx.x, grp = blockIdx.y, sp = blockIdx.z;
    const int k0 = sp * (NH / SPLITS);
    const int NS = (NH / SPLITS) / 64;               // 4

    float acc[2][4][4];
#pragma unroll
    for (int a = 0; a < 2; a++)
#pragma unroll
        for (int b = 0; b < 4; b++)
#pragma unroll
            for (int c = 0; c < 4; c++) acc[a][b][c] = 0.0f;

    const __half* aHsrc = (grp ? g_uM_h : g_uP_h) + (size_t)(mt * 128) * NH + k0;
    const __half* bHsrc = g_CsF_h + (size_t)grp * 128 * NH + k0;

#define G1FILL(slot, ko)                                          \
    do {                                                          \
        uint32_t st_ = sb + (slot) * STG1;                        \
        tile_async(st_,         aHsrc + (ko), NH, tid);           \
        tile_async(st_ + 16384, bHsrc + (ko), NH, tid);           \
        cp_commit();                                              \
    } while (0)

    const uint32_t aRow = (uint32_t)(wm * 32 + (lane & 15)) * 128 + ((lane >> 4) << 4);
    const uint32_t bRow = (uint32_t)(wn * 32 + (lane & 7)) * 128 + (((lane >> 3) & 1) << 4)
                          + ((lane >> 4) & 1) * 32;

    G1FILL(0, 0);
    G1FILL(1, 64);
    for (int s = 0; s < NS; s++) {
        if (s + 1 < NS) cp_wait<1>(); else cp_wait<0>();
        __syncthreads();
        if (s + 2 < NS) {
            int slot = (s + 2) % 3;
            G1FILL(slot, (s + 2) * 64);
        }
        uint32_t st = sb + (s % 3) * STG1;
        g1_step(st, st + 16384, aRow, bRow, acc);
    }

    const int g = lane >> 2, tig = lane & 3;
    const int mbase = mt * 128 + wm * 32;
    const int nbase = wn * 32;
#pragma unroll
    for (int mi = 0; mi < 2; mi++)
#pragma unroll
        for (int nj = 0; nj < 4; nj++) {
            int row = mbase + mi * 16 + g;
            int col = nbase + nj * 8 + tig * 2;
            float* p0 = g_part + ((size_t)(grp * SPLITS + sp) * Brows + row) * 128 + col;
            *(float2*)p0             = make_float2(acc[mi][nj][0], acc[mi][nj][1]);
            *(float2*)(p0 + 8 * 128) = make_float2(acc[mi][nj][2], acc[mi][nj][3]);
        }
}

// reduce splits + lam scale; SCALE^2 * 4096 = 2.0 exactly folded in here,
// epilogue divides by 4096 (exact power of 2).
__global__ void reduce_lam_kernel(const float* __restrict__ ms, int Brows) {
    int g = blockIdx.y;
    int idx = blockIdx.x * blockDim.x + threadIdx.x;
    int kp = idx & 127;
    float sum = 0.0f;
#pragma unroll
    for (int s = 0; s < SPLITS; s++)
        sum += g_part[(size_t)(g * SPLITS + s) * Brows * 128 + idx];
    float v = 2.0f * ms[g ? (2 * kp) : (2 * kp + 1)] * sum;
    if (g) g_Ao_h[idx] = __float2half(v);
    else   g_Ae_h[idx] = __float2half(v);
}

// ---------------------------------------------------------------------------
// GEMM2: single-term, fully resident. grid (8, 16), block 512.
// smem 128KB: A eo*32768 + kc*16384 (64KB); B 65536 + eo*32768 + kc*16384.
// Warp (wm,wn): 32 rows x 32 cols, dual e/o acc (64 floats). ONE barrier.
// ---------------------------------------------------------------------------
#define B2_BASE 65536
#define SMEM2_BYTES 131072

__global__ __launch_bounds__(512) void gemm2_hmma(float* __restrict__ phi) {
    extern __shared__ char sm[];
    const uint32_t sb = smem_u32(sm);
    const int tid = threadIdx.x, wid = tid >> 5, lane = tid & 31;
    const int wm = wid & 3, wn = wid >> 2;
    const int mt = blockIdx.x, nt = blockIdx.y;
    const float OSC = 1.0f / 4096.0f;

    // fills: A (4 tiles) + B (4 tiles), all 128x64
    {
        const size_t aoff = (size_t)(mt * 128) * 128;
#pragma unroll
        for (int kc = 0; kc < 2; kc++) {
            tile_async(sb +          kc * 16384, g_Ae_h + aoff + kc * 64, 128, tid);
            tile_async(sb + 32768 +  kc * 16384, g_Ao_h + aoff + kc * 64, 128, tid);
        }
#pragma unroll
        for (int eo = 0; eo < 2; eo++)
#pragma unroll
            for (int kc = 0; kc < 2; kc++) {
                size_t boff = (size_t)eo * NH * 128 + (size_t)(nt * 128) * 128 + kc * 64;
                tile_async(sb + B2_BASE + eo * 32768u + kc * 16384u, g_CsT_h + boff, 128, tid);
            }
        cp_commit();
    }

    const uint32_t aRow = (uint32_t)(wm * 32 + (lane & 15)) * 128 + ((lane >> 4) << 4);
    const uint32_t bRow = (uint32_t)(wn * 32 + (lane & 7)) * 128 + (((lane >> 3) & 1) << 4)
                          + ((lane >> 4) & 1) * 32;
    const int g = lane >> 2, tig = lane & 3;

    float acc[2][2][4][4];                       // [eo][mi][nj][4]
#pragma unroll
    for (int e = 0; e < 2; e++)
#pragma unroll
        for (int a = 0; a < 2; a++)
#pragma unroll
            for (int b = 0; b < 4; b++)
#pragma unroll
                for (int c = 0; c < 4; c++) acc[e][a][b][c] = 0.0f;

    cp_wait<0>();
    __syncthreads();

#pragma unroll
    for (int kc = 0; kc < 2; kc++) {
#pragma unroll
        for (int kp = 0; kp < 2; kp++) {
            const uint32_t kbp = kp * 64;
#pragma unroll
            for (int eo = 0; eo < 2; eo++) {
                uint32_t aBase = sb + eo * 32768u + kc * 16384u;
                uint32_t bBase = sb + B2_BASE + eo * 32768u + kc * 16384u;
                uint32_t bH[4][2][2];
#pragma unroll
                for (int nj = 0; nj < 4; nj++) {
                    uint32_t off = swz(bRow + nj * 8 * 128 + kbp);
                    ldsm_x4(bH[nj][0][0], bH[nj][0][1], bH[nj][1][0], bH[nj][1][1], bBase + off);
                }
#pragma unroll
                for (int ks = 0; ks < 2; ks++) {
                    const uint32_t kb = kbp + ks * 32;
                    uint32_t aH[2][4];
#pragma unroll
                    for (int mi = 0; mi < 2; mi++) {
                        uint32_t off = swz(aRow + mi * 16 * 128 + kb);
                        ldsm_x4(aH[mi][0], aH[mi][1], aH[mi][2], aH[mi][3], aBase + off);
                    }
#pragma unroll
                    for (int mi = 0; mi < 2; mi++)
#pragma unroll
                        for (int nj = 0; nj < 4; nj++)
                            mma_f16(acc[eo][mi][nj], aH[mi][0], aH[mi][1], aH[mi][2], aH[mi][3],
                                    bH[nj][ks][0], bH[nj][ks][1]);
                }
            }
        }
    }

    // register epilogue: phi[n'] = (e+o)/4096 ; phi[4095-n'] = (e-o)/4096
#pragma unroll
    for (int mi = 0; mi < 2; mi++)
#pragma unroll
        for (int nj = 0; nj < 4; nj++) {
#pragma unroll
            for (int half = 0; half < 2; half++) {
                int row = mt * 128 + wm * 32 + mi * 16 + half * 8 + g;
                int c = nt * 128 + wn * 32 + nj * 8 + tig * 2;
                float e0 = acc[0][mi][nj][half * 2];
                float e1 = acc[0][mi][nj][half * 2 + 1];
                float o0 = acc[1][mi][nj][half * 2];
                float o1 = acc[1][mi][nj][half * 2 + 1];
                float* rowp = phi + (size_t)row * N_GRID;
                *(float2*)(rowp + c) = make_float2((e0 + o0) * OSC, (e1 + o1) * OSC);
                *(float2*)(rowp + (4094 - c)) = make_float2((e1 - o1) * OSC, (e0 - o0) * OSC);
            }
        }
}

// ---------------------------------------------------------------------------
extern "C" void kernel_launch(void* const* d_in, const int* in_sizes, int n_in,
                              void* d_out, int out_size) {
    const float* rho = (const float*)d_in[0];
    const float* ms  = (const float*)d_in[1];
    float* phi = (float*)d_out;
    const int Brows = in_sizes[0] / N_GRID;

    cudaFuncSetAttribute(gemm1_hmma, cudaFuncAttributeMaxDynamicSharedMemorySize, SMEM1_BYTES);
    cudaFuncSetAttribute(gemm2_hmma, cudaFuncAttributeMaxDynamicSharedMemorySize, SMEM2_BYTES);

    prep_kernel<<<6144, 256>>>(rho);

    dim3 g1(Brows / 128, 2, SPLITS);
    gemm1_hmma<<<g1, 512, SMEM1_BYTES>>>(Brows);

    dim3 gr((Brows * 128) / 256, 2);
    reduce_lam_kernel<<<gr, 256>>>(ms, Brows);

    dim3 g2(Brows / 128, NH / 128);
    gemm2_hmma<<<g2, 512, SMEM2_BYTES>>>(phi);
}

// round 13
// speedup vs baseline: 1.5760x; 1.0013x over previous
#include <cuda_runtime.h>
#include <cuda_fp16.h>
#include <math.h>
#include <stdint.h>

#define N_GRID 4096
#define NH     2048
#define SPLITS 8
#define MAXB   1024

// ---------------- device scratch ----------------
__device__ __half g_uP_h [MAXB * NH];        // folded rho (fp16)
__device__ __half g_uM_h [MAXB * NH];
__device__ __half g_CsF_h[2 * 128 * NH];     // unscaled cos, [g][k'][n']
__device__ __half g_CsT_h[2 * NH * 128];     // unscaled cos, [g][n'][k']
__device__ float  g_part [16 * MAXB * 128];
__device__ __half g_Ae_h [MAXB * 128];       // 2*ms-scaled coeffs (fp16)
__device__ __half g_Ao_h [MAXB * 128];

// ---------------- helpers ----------------
__device__ __forceinline__ uint32_t smem_u32(const void* p) {
    uint32_t a;
    asm("{ .reg .u64 t; cvta.to.shared.u64 t, %1; cvt.u32.u64 %0, t; }" : "=r"(a) : "l"(p));
    return a;
}
__device__ __forceinline__ uint32_t swz(uint32_t off) { return off ^ ((off >> 3) & 0x70); }

__device__ __forceinline__ void cp16(uint32_t dst, const void* src) {
    asm volatile("cp.async.cg.shared.global [%0], [%1], 16;" :: "r"(dst), "l"(src));
}
__device__ __forceinline__ void cp_commit() {
    asm volatile("cp.async.commit_group;" ::: "memory");
}
template <int N>
__device__ __forceinline__ void cp_wait() {
    asm volatile("cp.async.wait_group %0;" :: "n"(N) : "memory");
}

__device__ __forceinline__ void ldsm_x4(uint32_t& r0, uint32_t& r1, uint32_t& r2, uint32_t& r3,
                                        uint32_t addr) {
    asm volatile("ldmatrix.sync.aligned.m8n8.x4.shared.b16 {%0,%1,%2,%3}, [%4];"
                 : "=r"(r0), "=r"(r1), "=r"(r2), "=r"(r3) : "r"(addr));
}
__device__ __forceinline__ void mma_f16(float* c, uint32_t a0, uint32_t a1, uint32_t a2,
                                        uint32_t a3, uint32_t b0, uint32_t b1) {
    asm volatile("mma.sync.aligned.m16n8k16.row.col.f32.f16.f16.f32 "
                 "{%0,%1,%2,%3}, {%4,%5,%6,%7}, {%8,%9}, {%0,%1,%2,%3};"
                 : "+f"(c[0]), "+f"(c[1]), "+f"(c[2]), "+f"(c[3])
                 : "r"(a0), "r"(a1), "r"(a2), "r"(a3), "r"(b0), "r"(b1));
}

union H4 { __half h[4]; uint2 v; };

// ---------------------------------------------------------------------------
__device__ __forceinline__ float cos_acc(float x) {
    const float INV_PIO2 = 0.6366197723675814f;
    float qf = rintf(x * INV_PIO2);
    int   iq = (int)qf;
    const float HI = 1.57079637050628662109375f;
    const float MD = -4.3711388286737929e-08f;
    const float LO = -1.7151245100059657e-15f;
    float r = fmaf(-qf, HI, x);
    r = fmaf(-qf, MD, r);
    r = fmaf(-qf, LO, r);
    float r2 = r * r;
    float pc = fmaf(r2,  2.4390448796e-05f, -1.3886763775e-03f);
    pc = fmaf(r2, pc,  4.1666623323e-02f);
    pc = fmaf(r2, pc, -4.9999999725e-01f);
    pc = fmaf(r2, pc,  1.0f);
    float ps = fmaf(r2,  2.7183114939e-06f, -1.9839334836e-04f);
    ps = fmaf(r2, ps,  8.3333293859e-03f);
    ps = fmaf(r2, ps, -1.6666666642e-01f);
    ps = r * fmaf(r2, ps, 1.0f);
    int n = iq & 3;
    float v = (n & 1) ? ps : pc;
    if (n == 1 || n == 2) v = -v;
    return v;
}

__device__ __forceinline__ float cs_raw(int n, int k) {
    const float PI_F = 3.1415927410125732421875f;
    float t1 = PI_F * (float)(2 * n + 1);
    float theta = (t1 * (float)k) * (1.0f / 8192.0f);
    return cos_acc(theta);
}

// ---------------------------------------------------------------------------
// prep: fold rho -> u fp16 ; build unscaled Cs tables (fp16)
// ---------------------------------------------------------------------------
__global__ void prep_kernel(const float* __restrict__ rho) {
    int bx = blockIdx.x;
    if (bx < 2048) {
        int t = bx * 256 + threadIdx.x;
        int b = t >> 9;
        int np = (t & 511) * 4;
        float4 f = *(const float4*)(rho + (size_t)b * N_GRID + np);
        float4 r = *(const float4*)(rho + (size_t)b * N_GRID + (4092 - np));
        H4 p, m;
        p.h[0] = __float2half(f.x + r.w); p.h[1] = __float2half(f.y + r.z);
        p.h[2] = __float2half(f.z + r.y); p.h[3] = __float2half(f.w + r.x);
        m.h[0] = __float2half(f.x - r.w); m.h[1] = __float2half(f.y - r.z);
        m.h[2] = __float2half(f.z - r.y); m.h[3] = __float2half(f.w - r.x);
        ((uint2*)g_uP_h)[t] = p.v;
        ((uint2*)g_uM_h)[t] = m.v;
    } else if (bx < 4096) {
        int t = (bx - 2048) * 256 + threadIdx.x;
        int g = t >> 18;
        int rem = t & 0x3FFFF;
        int kp = rem >> 11, np = rem & (NH - 1);
        int k = g ? (2 * kp + 1) : (2 * kp + 2);
        g_CsF_h[t] = __float2half(cs_raw(np, k));
    } else {
        int t = (bx - 4096) * 256 + threadIdx.x;
        int g = t >> 18;
        int rem = t & 0x3FFFF;
        int np = rem >> 7, kp = rem & 127;
        int k = g ? (2 * kp + 1) : (2 * kp + 2);
        g_CsT_h[t] = __float2half(cs_raw(np, k));
    }
}

// ---------------------------------------------------------------------------
__device__ __forceinline__ void tile_async(uint32_t dst, const __half* src,
                                           int stride, int tid) {          // 128x64
    const int row = tid >> 2;
    const int c0 = tid & 3;
    const char* s = (const char*)(src + (size_t)row * stride);
#pragma unroll
    for (int i = 0; i < 2; i++) {
        int ch = c0 + i * 4;
        cp16(dst + swz((uint32_t)row * 128 + ch * 16), s + ch * 16);
    }
}

// ---------------------------------------------------------------------------
// GEMM1 (unchanged R12): single-term, 3-stage ring, grid (8,2,8), 512 thr.
// ---------------------------------------------------------------------------
__device__ __forceinline__ void g1_step(uint32_t aB, uint32_t bB, uint32_t aRow,
                                        uint32_t bRow, float acc[2][4][4]) {
#pragma unroll
    for (int kp = 0; kp < 2; kp++) {
        const uint32_t kbp = kp * 64;
        uint32_t bH[4][2][2];
#pragma unroll
        for (int nj = 0; nj < 4; nj++) {
            uint32_t off = swz(bRow + nj * 8 * 128 + kbp);
            ldsm_x4(bH[nj][0][0], bH[nj][0][1], bH[nj][1][0], bH[nj][1][1], bB + off);
        }
#pragma unroll
        for (int ks = 0; ks < 2; ks++) {
            const uint32_t kb = kbp + ks * 32;
            uint32_t aH[2][4];
#pragma unroll
            for (int mi = 0; mi < 2; mi++) {
                uint32_t off = swz(aRow + mi * 16 * 128 + kb);
                ldsm_x4(aH[mi][0], aH[mi][1], aH[mi][2], aH[mi][3], aB + off);
            }
#pragma unroll
            for (int mi = 0; mi < 2; mi++)
#pragma unroll
                for (int nj = 0; nj < 4; nj++)
                    mma_f16(acc[mi][nj], aH[mi][0], aH[mi][1], aH[mi][2], aH[mi][3],
                            bH[nj][ks][0], bH[nj][ks][1]);
        }
    }
}

#define STG1 32768
#define SMEM1_BYTES (3 * STG1)

__global__ __launch_bounds__(512) void gemm1_hmma(int Brows) {
    extern __shared__ char sm[];
    const uint32_t sb = smem_u32(sm);
    const int tid = threadIdx.x, wid = tid >> 5, lane = tid & 31;
    const int wm = wid & 3, wn = wid >> 2;
    const int mt = blockIdx.x, grp = blockIdx.y, sp = blockIdx.z;
    const int k0 = sp * (NH / SPLITS);
    const int NS = (NH / SPLITS) / 64;               // 4

    float acc[2][4][4];
#pragma unroll
    for (int a = 0; a < 2; a++)
#pragma unroll
        for (int b = 0; b < 4; b++)
#pragma unroll
            for (int c = 0; c < 4; c++) acc[a][b][c] = 0.0f;

    const __half* aHsrc = (grp ? g_uM_h : g_uP_h) + (size_t)(mt * 128) * NH + k0;
    const __half* bHsrc = g_CsF_h + (size_t)grp * 128 * NH + k0;

#define G1FILL(slot, ko)                                          \
    do {                                                          \
        uint32_t st_ = sb + (slot) * STG1;                        \
        tile_async(st_,         aHsrc + (ko), NH, tid);           \
        tile_async(st_ + 16384, bHsrc + (ko), NH, tid);           \
        cp_commit();                                              \
    } while (0)

    const uint32_t aRow = (uint32_t)(wm * 32 + (lane & 15)) * 128 + ((lane >> 4) << 4);
    const uint32_t bRow = (uint32_t)(wn * 32 + (lane & 7)) * 128 + (((lane >> 3) & 1) << 4)
                          + ((lane >> 4) & 1) * 32;

    G1FILL(0, 0);
    G1FILL(1, 64);
    for (int s = 0; s < NS; s++) {
        if (s + 1 < NS) cp_wait<1>(); else cp_wait<0>();
        __syncthreads();
        if (s + 2 < NS) {
            int slot = (s + 2) % 3;
            G1FILL(slot, (s + 2) * 64);
        }
        uint32_t st = sb + (s % 3) * STG1;
        g1_step(st, st + 16384, aRow, bRow, acc);
    }

    const int g = lane >> 2, tig = lane & 3;
    const int mbase = mt * 128 + wm * 32;
    const int nbase = wn * 32;
#pragma unroll
    for (int mi = 0; mi < 2; mi++)
#pragma unroll
        for (int nj = 0; nj < 4; nj++) {
            int row = mbase + mi * 16 + g;
            int col = nbase + nj * 8 + tig * 2;
            float* p0 = g_part + ((size_t)(grp * SPLITS + sp) * Brows + row) * 128 + col;
            *(float2*)p0             = make_float2(acc[mi][nj][0], acc[mi][nj][1]);
            *(float2*)(p0 + 8 * 128) = make_float2(acc[mi][nj][2], acc[mi][nj][3]);
        }
}

// reduce splits + lam scale; 2.0 = SCALE^2*4096 folded here; epilogue /4096.
__global__ void reduce_lam_kernel(const float* __restrict__ ms, int Brows) {
    int g = blockIdx.y;
    int idx = blockIdx.x * blockDim.x + threadIdx.x;
    int kp = idx & 127;
    float sum = 0.0f;
#pragma unroll
    for (int s = 0; s < SPLITS; s++)
        sum += g_part[(size_t)(g * SPLITS + s) * Brows * 128 + idx];
    float v = 2.0f * ms[g ? (2 * kp) : (2 * kp + 1)] * sum;
    if (g) g_Ao_h[idx] = __float2half(v);
    else   g_Ae_h[idx] = __float2half(v);
}

// ---------------------------------------------------------------------------
// GEMM2 v6: fully resident (A 64KB @0: eo*32768+kc*16384;
// B 64KB @65536: eo*32768+kc*16384, rows n' 0..127). grid (8,16), 512 thr.
// h-loop: 2 phases x 64 cols; warp (wm,wn) = 32 rows x 16 cols dual-e/o,
// acc 32 floats -> no spills. Register e±o epilogue. ONE barrier.
// ---------------------------------------------------------------------------
#define B2_BASE 65536
#define SMEM2_BYTES 131072

__global__ __launch_bounds__(512) void gemm2_hmma(float* __restrict__ phi) {
    extern __shared__ char sm[];
    const uint32_t sb = smem_u32(sm);
    const int tid = threadIdx.x, wid = tid >> 5, lane = tid & 31;
    const int wm = wid & 3, wn = wid >> 2;
    const int mt = blockIdx.x, nt = blockIdx.y;
    const float OSC = 1.0f / 4096.0f;

    {
        const size_t aoff = (size_t)(mt * 128) * 128;
#pragma unroll
        for (int kc = 0; kc < 2; kc++) {
            tile_async(sb +          kc * 16384, g_Ae_h + aoff + kc * 64, 128, tid);
            tile_async(sb + 32768 +  kc * 16384, g_Ao_h + aoff + kc * 64, 128, tid);
        }
#pragma unroll
        for (int eo = 0; eo < 2; eo++)
#pragma unroll
            for (int kc = 0; kc < 2; kc++) {
                size_t boff = (size_t)eo * NH * 128 + (size_t)(nt * 128) * 128 + kc * 64;
                tile_async(sb + B2_BASE + eo * 32768u + kc * 16384u, g_CsT_h + boff, 128, tid);
            }
        cp_commit();
    }

    const uint32_t aRow = (uint32_t)(wm * 32 + (lane & 15)) * 128 + ((lane >> 4) << 4);
    const int g = lane >> 2, tig = lane & 3;

    cp_wait<0>();
    __syncthreads();

    for (int h = 0; h < 2; h++) {
        // B rows for this phase: n' = h*64 + wn*16 + nj*8 (+ lane bits)
        const uint32_t bRow = (uint32_t)(h * 64 + wn * 16 + (lane & 7)) * 128
                              + (((lane >> 3) & 1) << 4) + ((lane >> 4) & 1) * 32;

        float acc[2][2][2][4];                       // [eo][mi][nj][4]
#pragma unroll
        for (int e = 0; e < 2; e++)
#pragma unroll
            for (int a = 0; a < 2; a++)
#pragma unroll
                for (int b = 0; b < 2; b++)
#pragma unroll
                    for (int c = 0; c < 4; c++) acc[e][a][b][c] = 0.0f;

#pragma unroll
        for (int kc = 0; kc < 2; kc++) {
#pragma unroll
            for (int kp = 0; kp < 2; kp++) {
                const uint32_t kbp = kp * 64;
#pragma unroll
                for (int eo = 0; eo < 2; eo++) {
                    uint32_t aBase = sb + eo * 32768u + kc * 16384u;
                    uint32_t bBase = sb + B2_BASE + eo * 32768u + kc * 16384u;
                    uint32_t bH[2][2][2];
#pragma unroll
                    for (int nj = 0; nj < 2; nj++) {
                        uint32_t off = swz(bRow + nj * 8 * 128 + kbp);
                        ldsm_x4(bH[nj][0][0], bH[nj][0][1], bH[nj][1][0], bH[nj][1][1], bBase + off);
                    }
#pragma unroll
                    for (int ks = 0; ks < 2; ks++) {
                        const uint32_t kb = kbp + ks * 32;
                        uint32_t aH[2][4];
#pragma unroll
                        for (int mi = 0; mi < 2; mi++) {
                            uint32_t off = swz(aRow + mi * 16 * 128 + kb);
                            ldsm_x4(aH[mi][0], aH[mi][1], aH[mi][2], aH[mi][3], aBase + off);
                        }
#pragma unroll
                        for (int mi = 0; mi < 2; mi++)
#pragma unroll
                            for (int nj = 0; nj < 2; nj++)
                                mma_f16(acc[eo][mi][nj], aH[mi][0], aH[mi][1], aH[mi][2], aH[mi][3],
                                        bH[nj][ks][0], bH[nj][ks][1]);
                    }
                }
            }
        }

        // register epilogue: phi[n'] = (e+o)/4096 ; phi[4095-n'] = (e-o)/4096
#pragma unroll
        for (int mi = 0; mi < 2; mi++)
#pragma unroll
            for (int nj = 0; nj < 2; nj++) {
#pragma unroll
                for (int half = 0; half < 2; half++) {
                    int row = mt * 128 + wm * 32 + mi * 16 + half * 8 + g;
                    int c = nt * 128 + h * 64 + wn * 16 + nj * 8 + tig * 2;
                    float e0 = acc[0][mi][nj][half * 2];
                    float e1 = acc[0][mi][nj][half * 2 + 1];
                    float o0 = acc[1][mi][nj][half * 2];
                    float o1 = acc[1][mi][nj][half * 2 + 1];
                    float* rowp = phi + (size_t)row * N_GRID;
                    *(float2*)(rowp + c) = make_float2((e0 + o0) * OSC, (e1 + o1) * OSC);
                    *(float2*)(rowp + (4094 - c)) = make_float2((e1 - o1) * OSC, (e0 - o0) * OSC);
                }
            }
    }
}

// ---------------------------------------------------------------------------
extern "C" void kernel_launch(void* const* d_in, const int* in_sizes, int n_in,
                              void* d_out, int out_size) {
    const float* rho = (const float*)d_in[0];
    const float* ms  = (const float*)d_in[1];
    float* phi = (float*)d_out;
    const int Brows = in_sizes[0] / N_GRID;

    cudaFuncSetAttribute(gemm1_hmma, cudaFuncAttributeMaxDynamicSharedMemorySize, SMEM1_BYTES);
    cudaFuncSetAttribute(gemm2_hmma, cudaFuncAttributeMaxDynamicSharedMemorySize, SMEM2_BYTES);

    prep_kernel<<<6144, 256>>>(rho);

    dim3 g1(Brows / 128, 2, SPLITS);
    gemm1_hmma<<<g1, 512, SMEM1_BYTES>>>(Brows);

    dim3 gr((Brows * 128) / 256, 2);
    reduce_lam_kernel<<<gr, 256>>>(ms, Brows);

    dim3 g2(Brows / 128, NH / 128);
    gemm2_hmma<<<g2, 512, SMEM2_BYTES>>>(phi);
}